// round 13
// baseline (speedup 1.0000x reference)
#include <cuda_runtime.h>
#include <math.h>
#include <stdint.h>

#define DIMF 128
#define N_LEGO 50000
#define N_POINT 100000
#define NE_LL 500000
#define NE_PP 400000
#define NE_LP 500000
#define NE_PL 500000
#define NEG_INF_KEY 0x007FFFFFu
#define SCAN_B 512

// ---------------- scratch ----------------
__device__ float    g_xl[N_LEGO * DIMF];
__device__ float    g_xp[N_POINT * DIMF];
__device__ float    g_la[N_LEGO * DIMF];
__device__ float    g_pa[N_POINT * DIMF];
__device__ float    g_ss[N_POINT];
__device__ float    g_sd[N_POINT];
__device__ float    g_escore[NE_LL];
__device__ float    g_QK[(size_t)N_LEGO * 640];
__device__ float    g_PQ[(size_t)N_POINT * 1152];
__device__ unsigned g_emax[N_POINT * DIMF];
__device__ float    g_WcatT[4 * 128 * 640];
__device__ float    g_bcatT[4 * 640];
__device__ float    g_WcatE[4 * 128 * 1152];
__device__ float    g_wadall[4 * 128];
// sort scratch + sorted edge lists + CSR rowptrs
__device__ int g_hist[N_POINT], g_work[N_POINT], g_bsum[SCAN_B];
__device__ int g_sll_s[NE_LL];
__device__ int g_spp_s[NE_PP], g_spp_d[NE_PP];
__device__ int g_slp_s[NE_LP];
__device__ int g_spl_s[NE_PL];
__device__ int g_rp_ll[N_LEGO + 1], g_rp_lp[N_POINT + 1], g_rp_pl[N_LEGO + 1];

// ---------------- helpers ----------------
__device__ __forceinline__ unsigned fkey(float f) {
    unsigned u = __float_as_uint(f);
    return (u & 0x80000000u) ? ~u : (u | 0x80000000u);
}
__device__ __forceinline__ float fdecode(unsigned kk) {
    unsigned u = (kk & 0x80000000u) ? (kk ^ 0x80000000u) : ~kk;
    return __uint_as_float(u);
}
__device__ __forceinline__ uint2 bfsplit2(float v0, float v1) {
    uint32_t h, m;
    asm("cvt.rn.bf16x2.f32 %0, %1, %2;" : "=r"(h) : "f"(v1), "f"(v0));
    float h0 = __uint_as_float(h << 16);
    float h1 = __uint_as_float(h & 0xffff0000u);
    asm("cvt.rn.bf16x2.f32 %0, %1, %2;" : "=r"(m) : "f"(v1 - h1), "f"(v0 - h0));
    return make_uint2(h, m);
}

// ---------------- GEMM (round-7/8 WIN core; +ldb param only) ----------------
#define AHS 20
#define BHS 136
#define AH_OFF 0
#define AM_OFF 2560
#define BH_OFF 5120
#define BM_OFF 7296
#define STAGE_U 9472
#define SMEM_BYTES (2 * STAGE_U * 4)

#define MMA_BF16(accv, a0, a1, a2, a3, b0, b1)                                     \
    asm("mma.sync.aligned.m16n8k16.row.col.f32.bf16.bf16.f32 "                     \
        "{%0,%1,%2,%3}, {%4,%5,%6,%7}, {%8,%9}, {%0,%1,%2,%3};"                    \
        : "+f"(accv[0]), "+f"(accv[1]), "+f"(accv[2]), "+f"(accv[3])               \
        : "r"(a0), "r"(a1), "r"(a2), "r"(a3), "r"(b0), "r"(b1))

#define BF_COMPUTE(sb)                                                             \
    {                                                                              \
        _Pragma("unroll")                                                          \
        for (int kc = 0; kc < 2; kc++) {                                           \
            uint32_t ah[2][4], am[2][4];                                           \
            _Pragma("unroll")                                                      \
            for (int mt = 0; mt < 2; mt++) {                                       \
                int r0 = wm + mt * 16 + g;                                         \
                int o0 = r0 * AHS + kc * 8 + t, o1 = (r0 + 8) * AHS + kc * 8 + t;  \
                ah[mt][0] = (sb)[AH_OFF + o0];     ah[mt][1] = (sb)[AH_OFF + o1];  \
                ah[mt][2] = (sb)[AH_OFF + o0 + 4]; ah[mt][3] = (sb)[AH_OFF + o1 + 4]; \
                am[mt][0] = (sb)[AM_OFF + o0];     am[mt][1] = (sb)[AM_OFF + o1];  \
                am[mt][2] = (sb)[AM_OFF + o0 + 4]; am[mt][3] = (sb)[AM_OFF + o1 + 4]; \
            }                                                                      \
            _Pragma("unroll")                                                      \
            for (int nt = 0; nt < 8; nt++) {                                       \
                int nn = wn + nt * 8 + g;                                          \
                int p0 = (kc * 8 + t) * BHS + nn, p1 = (kc * 8 + t + 4) * BHS + nn;\
                uint32_t b0h = (sb)[BH_OFF + p0], b1h = (sb)[BH_OFF + p1];         \
                uint32_t b0m = (sb)[BM_OFF + p0], b1m = (sb)[BM_OFF + p1];         \
                _Pragma("unroll")                                                  \
                for (int mt = 0; mt < 2; mt++) {                                   \
                    MMA_BF16(acc[mt][nt], am[mt][0], am[mt][1], am[mt][2],         \
                             am[mt][3], b0h, b1h);                                 \
                    MMA_BF16(acc[mt][nt], ah[mt][0], ah[mt][1], ah[mt][2],         \
                             ah[mt][3], b0m, b1m);                                 \
                    MMA_BF16(acc[mt][nt], ah[mt][0], ah[mt][1], ah[mt][2],         \
                             ah[mt][3], b0h, b1h);                                 \
                }                                                                  \
            }                                                                      \
        }                                                                          \
    }

#define STS_A4(sb, row, c4, v4)                                                    \
    {                                                                              \
        int k2c = (c4) >> 1;                                                       \
        uint2 p01 = bfsplit2((v4).x, (v4).y);                                      \
        uint2 p23 = bfsplit2((v4).z, (v4).w);                                      \
        *(uint2*)((sb) + AH_OFF + (row) * AHS + k2c) = make_uint2(p01.x, p23.x);   \
        *(uint2*)((sb) + AM_OFF + (row) * AHS + k2c) = make_uint2(p01.y, p23.y);   \
    }
#define STS_B4(sb, k2, c4, v0, v1)                                                 \
    {                                                                              \
        uint2 q0 = bfsplit2((v0).x, (v1).x);                                       \
        uint2 q1 = bfsplit2((v0).y, (v1).y);                                       \
        uint2 q2 = bfsplit2((v0).z, (v1).z);                                       \
        uint2 q3 = bfsplit2((v0).w, (v1).w);                                       \
        *(uint4*)((sb) + BH_OFF + (k2) * BHS + (c4)) = make_uint4(q0.x, q1.x, q2.x, q3.x); \
        *(uint4*)((sb) + BM_OFF + (k2) * BHS + (c4)) = make_uint4(q0.y, q1.y, q2.y, q3.y); \
    }

__global__ __launch_bounds__(256, 2) void bf3_gemm_kernel(
    const float* __restrict__ A, const float* __restrict__ B, int ldb,
    const float* __restrict__ bias, float* __restrict__ C,
    int M, int N, int K)
{
    extern __shared__ uint32_t smu[];
    const int tid = threadIdx.x;
    const int warp = tid >> 5, lane = tid & 31;
    const int g = lane >> 2, t = lane & 3;
    const int warp_m = warp & 3, warp_n = warp >> 2;
    const int m_base = blockIdx.y * 128, n_base = blockIdx.x * 128;
    const int wm = warp_m * 32, wn = warp_n * 64;
    const int a_row = tid >> 3, a_c4 = (tid & 7) * 4;
    const int b_k2 = tid >> 5, b_c4 = (tid & 31) * 4;

    float acc[2][8][4];
#pragma unroll
    for (int i = 0; i < 2; i++)
#pragma unroll
        for (int j = 0; j < 8; j++)
#pragma unroll
            for (int c = 0; c < 4; c++) acc[i][j][c] = 0.f;

    float4 av[4], bv0[2], bv1[2];
    const float4 f4z = make_float4(0.f, 0.f, 0.f, 0.f);

#define GEN_LDG(kt)                                                                \
    {                                                                              \
        _Pragma("unroll")                                                          \
        for (int i = 0; i < 4; i++) {                                              \
            int row = a_row + i * 32, gr = m_base + row;                           \
            av[i] = (gr < M) ? *(const float4*)(A + (size_t)gr * K + (kt) + a_c4)  \
                             : f4z;                                                \
        }                                                                          \
        _Pragma("unroll")                                                          \
        for (int i = 0; i < 2; i++) {                                              \
            int k2 = b_k2 + i * 8;                                                 \
            bv0[i] = *(const float4*)(B + (size_t)((kt) + 2 * k2) * ldb + n_base + b_c4);     \
            bv1[i] = *(const float4*)(B + (size_t)((kt) + 2 * k2 + 1) * ldb + n_base + b_c4); \
        }                                                                          \
    }
#define GEN_STS(st)                                                                \
    {                                                                              \
        uint32_t* sb = smu + (st) * STAGE_U;                                       \
        _Pragma("unroll")                                                          \
        for (int i = 0; i < 4; i++) STS_A4(sb, a_row + i * 32, a_c4, av[i]);       \
        _Pragma("unroll")                                                          \
        for (int i = 0; i < 2; i++) STS_B4(sb, b_k2 + i * 8, b_c4, bv0[i], bv1[i]);\
    }

    GEN_LDG(0);
    int stage = 0;
    for (int kt = 0; kt < K; kt += 32, stage ^= 1) {
        GEN_STS(stage);
        __syncthreads();
        if (kt + 32 < K) GEN_LDG(kt + 32);
        const uint32_t* sb = smu + stage * STAGE_U;
        BF_COMPUTE(sb);
    }

#pragma unroll
    for (int mt = 0; mt < 2; mt++) {
        int r0 = m_base + wm + mt * 16 + g, r1 = r0 + 8;
#pragma unroll
        for (int nt = 0; nt < 8; nt++) {
            int c = n_base + wn + nt * 8 + 2 * t;
            float b0 = 0.f, b1 = 0.f;
            if (bias) { b0 = bias[c]; b1 = bias[c + 1]; }
            if (r0 < M) *(float2*)(C + (size_t)r0 * N + c) =
                make_float2(acc[mt][nt][0] + b0, acc[mt][nt][1] + b1);
            if (r1 < M) *(float2*)(C + (size_t)r1 * N + c) =
                make_float2(acc[mt][nt][2] + b0, acc[mt][nt][3] + b1);
        }
    }
}

// ---------------- fused EdgeConv MLP2 + segment-max (round-8 WIN; +pqs stride) ----------------
__global__ __launch_bounds__(256, 2) void edge_bf3_kernel(
    const float* __restrict__ PQ, int pqs, const float* __restrict__ b1,
    const float* __restrict__ W2,
    const int* __restrict__ src, const int* __restrict__ dst,
    unsigned* __restrict__ emax, int E)
{
    extern __shared__ uint32_t smu[];
    __shared__ int se[128], de[128];
    const int tid = threadIdx.x;
    const int warp = tid >> 5, lane = tid & 31;
    const int g = lane >> 2, t = lane & 3;
    const int warp_m = warp & 3, warp_n = warp >> 2;
    const int e_base = blockIdx.y * 128;
    const int wm = warp_m * 32, wn = warp_n * 64;
    const int a_row = tid >> 3, a_c4 = (tid & 7) * 4;
    const int b_k2 = tid >> 5, b_c4 = (tid & 31) * 4;

    if (tid < 128) {
        int e = e_base + tid;
        bool ok = (e < E);
        se[tid] = ok ? src[e] : 0;
        de[tid] = ok ? dst[e] : 0;
    }
    __syncthreads();

    float acc[2][8][4];
#pragma unroll
    for (int i = 0; i < 2; i++)
#pragma unroll
        for (int j = 0; j < 8; j++)
#pragma unroll
            for (int c = 0; c < 4; c++) acc[i][j][c] = 0.f;

    float4 bv0[2], bv1[2];

#define EB_LDG(kt)                                                                 \
    {                                                                              \
        _Pragma("unroll")                                                          \
        for (int i = 0; i < 2; i++) {                                              \
            int k2 = b_k2 + i * 8;                                                 \
            bv0[i] = *(const float4*)(W2 + (size_t)((kt) + 2 * k2) * 128 + b_c4);     \
            bv1[i] = *(const float4*)(W2 + (size_t)((kt) + 2 * k2 + 1) * 128 + b_c4); \
        }                                                                          \
    }
#define EB_B_STS(st)                                                               \
    {                                                                              \
        uint32_t* sb = smu + (st) * STAGE_U;                                       \
        _Pragma("unroll")                                                          \
        for (int i = 0; i < 2; i++) STS_B4(sb, b_k2 + i * 8, b_c4, bv0[i], bv1[i]);\
    }
#define EB_A_STS(kt, st)                                                           \
    {                                                                              \
        uint32_t* sb = smu + (st) * STAGE_U;                                       \
        float4 bb = *(const float4*)(b1 + (kt) + a_c4);                            \
        _Pragma("unroll")                                                          \
        for (int i = 0; i < 4; i++) {                                              \
            int row = a_row + i * 32;                                              \
            size_t dof = (size_t)de[row] * pqs, sof = (size_t)se[row] * pqs + 512; \
            float4 rv = *(const float4*)(PQ + dof + (kt) + a_c4);                  \
            float4 qv = *(const float4*)(PQ + sof + (kt) + a_c4);                  \
            float4 h;                                                              \
            h.x = fmaxf(rv.x + qv.x + bb.x, 0.f);                                  \
            h.y = fmaxf(rv.y + qv.y + bb.y, 0.f);                                  \
            h.z = fmaxf(rv.z + qv.z + bb.z, 0.f);                                  \
            h.w = fmaxf(rv.w + qv.w + bb.w, 0.f);                                  \
            STS_A4(sb, row, a_c4, h);                                              \
        }                                                                          \
    }

    EB_A_STS(0, 0);
    EB_LDG(0);
    int stage = 0;
    for (int kt = 0; kt < 512; kt += 32, stage ^= 1) {
        EB_B_STS(stage);
        __syncthreads();
        if (kt + 32 < 512) EB_LDG(kt + 32);
        const uint32_t* sb = smu + stage * STAGE_U;
        BF_COMPUTE(sb);
        if (kt + 32 < 512) EB_A_STS(kt + 32, stage ^ 1);
    }

#pragma unroll
    for (int mt = 0; mt < 2; mt++) {
        int r0 = wm + mt * 16 + g, r1 = r0 + 8;
        int e0 = e_base + r0, e1 = e_base + r1;
        int d0 = de[r0], d1 = de[r1];
#pragma unroll
        for (int nt = 0; nt < 8; nt++) {
            int c = wn + nt * 8 + 2 * t;
            if (e0 < E) {
                atomicMax(emax + (size_t)d0 * DIMF + c,     fkey(acc[mt][nt][0]));
                atomicMax(emax + (size_t)d0 * DIMF + c + 1, fkey(acc[mt][nt][1]));
            }
            if (e1 < E) {
                atomicMax(emax + (size_t)d1 * DIMF + c,     fkey(acc[mt][nt][2]));
                atomicMax(emax + (size_t)d1 * DIMF + c + 1, fkey(acc[mt][nt][3]));
            }
        }
    }
}

// ---------------- CSR-fused attention kernels ----------------
// one warp per dst: out = skip + softmax-aggregated V (no atomics, no prior copy)
__global__ void trans_fused_kernel(
    const float* __restrict__ qkvs, int qs, const int* __restrict__ rowptr,
    const int* __restrict__ srcs, float* __restrict__ escore,
    float* __restrict__ out, int n, float scale)
{
    int idx = blockIdx.x * blockDim.x + threadIdx.x;
    int d = idx >> 5, lane = idx & 31;
    if (d >= n) return;
    float4 o = *(const float4*)(qkvs + (size_t)d * qs + 384 + lane * 4);  // skip
    int beg = rowptr[d], end = rowptr[d + 1];
    if (beg < end) {
        float4 q = *(const float4*)(qkvs + (size_t)d * qs + lane * 4);
        float m = -INFINITY;
        for (int e = beg; e < end; e++) {
            int s0 = srcs[e];
            float4 kv = *(const float4*)(qkvs + (size_t)s0 * qs + 128 + lane * 4);
            float s = q.x * kv.x + q.y * kv.y + q.z * kv.z + q.w * kv.w;
#pragma unroll
            for (int oo = 16; oo; oo >>= 1) s += __shfl_xor_sync(0xffffffffu, s, oo);
            s *= scale;
            if (lane == 0) escore[e] = s;
            m = fmaxf(m, s);
        }
        __syncwarp();
        float4 acc = make_float4(0.f, 0.f, 0.f, 0.f);
        float dsum = 0.f;
        for (int e = beg; e < end; e++) {
            float ex = expf(escore[e] - m);
            dsum += ex;
            int s0 = srcs[e];
            float4 vv = *(const float4*)(qkvs + (size_t)s0 * qs + 256 + lane * 4);
            acc.x += ex * vv.x; acc.y += ex * vv.y;
            acc.z += ex * vv.z; acc.w += ex * vv.w;
        }
        float inv = 1.f / (dsum + 1e-16f);
        o.x += acc.x * inv; o.y += acc.y * inv;
        o.z += acc.z * inv; o.w += acc.w * inv;
    }
    *(float4*)(out + (size_t)d * DIMF + lane * 4) = o;
}

__global__ void gat_fused_kernel(
    const float* __restrict__ ss, const float* __restrict__ sd,
    const float* __restrict__ hs, int hstride, const int* __restrict__ rowptr,
    const int* __restrict__ srcs, float* __restrict__ escore,
    float* __restrict__ out, int n)
{
    int idx = blockIdx.x * blockDim.x + threadIdx.x;
    int d = idx >> 5, lane = idx & 31;
    if (d >= n) return;
    int beg = rowptr[d], end = rowptr[d + 1];
    if (beg == end) return;
    float sdd = sd[d];
    float m = -INFINITY;
    for (int e = beg + lane; e < end; e += 32) {
        float s = ss[srcs[e]] + sdd;
        s = (s > 0.f) ? s : 0.2f * s;
        escore[e] = s;
        m = fmaxf(m, s);
    }
#pragma unroll
    for (int o = 16; o; o >>= 1) m = fmaxf(m, __shfl_xor_sync(0xffffffffu, m, o));
    __syncwarp();
    float4 acc = make_float4(0.f, 0.f, 0.f, 0.f);
    float dsum = 0.f;
    for (int e = beg; e < end; e++) {
        float ex = expf(escore[e] - m);
        dsum += ex;
        int s0 = srcs[e];
        float4 hv = *(const float4*)(hs + (size_t)s0 * hstride + lane * 4);
        acc.x += ex * hv.x; acc.y += ex * hv.y;
        acc.z += ex * hv.z; acc.w += ex * hv.w;
    }
    float inv = 1.f / (dsum + 1e-16f);
    float* op = out + (size_t)d * DIMF + lane * 4;
    float4 o = *(float4*)op;
    o.x += acc.x * inv; o.y += acc.y * inv;
    o.z += acc.z * inv; o.w += acc.w * inv;
    *(float4*)op = o;
}

// ---------------- one-time weight prep ----------------
// WcatT[inst][128][640] = [Wq|Wk|Wv|Ws|gW[inst]], bcat stride 640 (gat cols 0)
__global__ void concat_trans_kernel(const float* Wq, const float* Wk, const float* Wv,
                                    const float* Ws, const float* bq, const float* bk,
                                    const float* bv, const float* bs, const float* gW,
                                    float* Wcat, float* bcat)
{
    int i = blockIdx.x * blockDim.x + threadIdx.x;
    if (i >= 4 * 128 * 640) return;
    int inst = i / (128 * 640), rem = i % (128 * 640);
    int r = rem / 640, j = rem % 640;
    float v;
    if (j < 512) {
        int sel = j >> 7, jj = j & 127;
        const float* W = sel == 0 ? Wq : sel == 1 ? Wk : sel == 2 ? Wv : Ws;
        v = W[((size_t)inst * 128 + r) * 128 + jj];
    } else {
        v = gW[((size_t)inst * 128 + r) * 128 + (j - 512)];
    }
    Wcat[i] = v;
    if (r == 0) {
        float b = 0.f;
        if (j < 512) {
            int sel = j >> 7, jj = j & 127;
            const float* bb = sel == 0 ? bq : sel == 1 ? bk : sel == 2 ? bv : bs;
            b = bb[inst * 128 + jj];
        }
        bcat[inst * 640 + j] = b;
    }
}
// WcatE[inst][128][1152] = [W1a-W1b | W1b | gW[(inst+1)&3]]
__global__ void concat_edge_kernel(const float* W1, const float* gW, float* Wcat)
{
    int i = blockIdx.x * blockDim.x + threadIdx.x;
    if (i >= 4 * 128 * 1152) return;
    int inst = i / (128 * 1152), rem = i % (128 * 1152);
    int r = rem / 1152, j = rem % 1152;
    const float* Wi = W1 + (size_t)inst * 256 * 512;
    float v;
    if (j < 512)       v = Wi[(size_t)r * 512 + j] - Wi[(size_t)(128 + r) * 512 + j];
    else if (j < 1024) v = Wi[(size_t)(128 + r) * 512 + (j - 512)];
    else               v = gW[((size_t)((inst + 1) & 3) * 128 + r) * 128 + (j - 1024)];
    Wcat[i] = v;
}
__global__ void wadall_kernel(const float* __restrict__ gW, const float* __restrict__ gAd,
                              float* __restrict__ wad)
{
    int b = blockIdx.x, j = threadIdx.x;
    float s = 0.f;
    for (int kk = 0; kk < 128; kk++)
        s += gW[((size_t)b * 128 + j) * 128 + kk] * gAd[b * 128 + kk];
    wad[b * 128 + j] = s;
}

// ---------------- counting sort by dst + rowptr ----------------
__global__ void fill_i32_kernel(int* p, int val, int n) {
    int i = blockIdx.x * blockDim.x + threadIdx.x;
    if (i < n) p[i] = val;
}
__global__ void count_kernel(const int* __restrict__ dst, int* __restrict__ hist, int E) {
    int e = blockIdx.x * blockDim.x + threadIdx.x;
    if (e < E) atomicAdd(hist + dst[e], 1);
}
__global__ void scan1_kernel(const int* __restrict__ hist, int* __restrict__ off,
                             int* __restrict__ bsum, int n) {
    __shared__ int sh[SCAN_B];
    int tid = threadIdx.x, i = blockIdx.x * SCAN_B + tid;
    int v = (i < n) ? hist[i] : 0;
    sh[tid] = v; __syncthreads();
    for (int d = 1; d < SCAN_B; d <<= 1) {
        int t2 = (tid >= d) ? sh[tid - d] : 0;
        __syncthreads(); sh[tid] += t2; __syncthreads();
    }
    if (i < n) off[i] = sh[tid] - v;
    if (tid == SCAN_B - 1) bsum[blockIdx.x] = sh[tid];
}
__global__ void scan2_kernel(int* __restrict__ bsum, int nb) {
    __shared__ int sh[SCAN_B];
    int tid = threadIdx.x;
    int v = (tid < nb) ? bsum[tid] : 0;
    sh[tid] = v; __syncthreads();
    for (int d = 1; d < SCAN_B; d <<= 1) {
        int t2 = (tid >= d) ? sh[tid - d] : 0;
        __syncthreads(); sh[tid] += t2; __syncthreads();
    }
    if (tid < nb) bsum[tid] = sh[tid] - v;
}
__global__ void scan3_kernel(const int* __restrict__ off, const int* __restrict__ bsum,
                             int* __restrict__ work, int* __restrict__ rowptr,
                             int n, int E) {
    int i = blockIdx.x * blockDim.x + threadIdx.x;
    if (i < n) {
        int v = off[i] + bsum[i / SCAN_B];
        work[i] = v;
        if (rowptr) rowptr[i] = v;
    }
    if (i == 0 && rowptr) rowptr[n] = E;
}
__global__ void scatter_kernel(const int* __restrict__ src, const int* __restrict__ dst,
                               int* __restrict__ work,
                               int* __restrict__ osrc, int* __restrict__ odst, int E) {
    int e = blockIdx.x * blockDim.x + threadIdx.x;
    if (e >= E) return;
    int d = dst[e];
    int pos = atomicAdd(work + d, 1);
    osrc[pos] = src[e];
    if (odst) odst[pos] = d;
}

// ---------------- small glue kernels ----------------
__global__ void fill_u32_kernel(unsigned* p, unsigned val, int n) {
    int i = blockIdx.x * blockDim.x + threadIdx.x;
    if (i < n) p[i] = val;
}
__global__ void node_dot_kernel(const float* __restrict__ h, int hstride,
                                const float* __restrict__ avec,
                                float* __restrict__ out, int n)
{
    int idx = blockIdx.x * blockDim.x + threadIdx.x;
    int i = idx >> 5, lane = idx & 31;
    if (i >= n) return;
    float4 hv = *(const float4*)(h + (size_t)i * hstride + lane * 4);
    float4 av = *(const float4*)(avec + lane * 4);
    float s = hv.x * av.x + hv.y * av.y + hv.z * av.z + hv.w * av.w;
#pragma unroll
    for (int o = 16; o; o >>= 1) s += __shfl_xor_sync(0xffffffffu, s, o);
    if (lane == 0) out[i] = s;
}
__global__ void bias_add_kernel(float* __restrict__ out, const float* __restrict__ b, int n) {
    int i = blockIdx.x * blockDim.x + threadIdx.x;
    if (i >= n * 32) return;
    int f = (i & 31) * 4;
    float4 bv = *(const float4*)(b + f);
    float4 ov = *(float4*)(out + (size_t)i * 4);
    ov.x += bv.x; ov.y += bv.y; ov.z += bv.z; ov.w += bv.w;
    *(float4*)(out + (size_t)i * 4) = ov;
}
__global__ void finalize_max_b2_kernel(const unsigned* __restrict__ emax,
                                       const float* __restrict__ b2,
                                       float* __restrict__ out, int total) {
    int i = blockIdx.x * blockDim.x + threadIdx.x;
    if (i >= total) return;
    float v = fdecode(emax[i]);
    out[i] = isfinite(v) ? v + b2[i & (DIMF - 1)] : 0.f;
}

// ---------------- host orchestration ----------------
static inline int div_up(int a, int b) { return (a + b - 1) / b; }

struct Scratch {
    float *xl, *xp, *la, *pa, *ss, *sd, *escore, *QK, *PQ;
    float *WcatT, *bcatT, *WcatE, *wadall;
    unsigned *emax;
    int *hist, *work, *bsum;
    int *sll_s, *spp_s, *spp_d, *slp_s, *spl_s;
    int *rp_ll, *rp_lp, *rp_pl;
};

static void sort_graph(const Scratch& S, const int* src, const int* dst, int E, int n,
                       int* osrc, int* odst, int* rowptr)
{
    fill_i32_kernel<<<div_up(n, 256), 256>>>(S.hist, 0, n);
    count_kernel<<<div_up(E, 256), 256>>>(dst, S.hist, E);
    int nb = div_up(n, SCAN_B);
    scan1_kernel<<<nb, SCAN_B>>>(S.hist, S.work, S.bsum, n);
    scan2_kernel<<<1, SCAN_B>>>(S.bsum, nb);
    scan3_kernel<<<div_up(n, 256), 256>>>(S.work, S.bsum, S.hist, rowptr, n, E);
    scatter_kernel<<<div_up(E, 256), 256>>>(src, dst, S.hist, osrc, odst, E);
}

static void sgemm(const float* A, const float* B, int ldb, const float* bias, float* C,
                  int M, int N, int K) {
    dim3 grid(N / 128, div_up(M, 128));
    bf3_gemm_kernel<<<grid, 256, SMEM_BYTES>>>(A, B, ldb, bias, C, M, N, K);
}

static void gat_tail(const Scratch& S, const float* hs, int hstride, int ns,
                     const float* xd, int nd, const int* rowptr, const int* srcs,
                     int inst, const float* gAs, const float* gb, float* out)
{
    node_dot_kernel<<<div_up(ns * 32, 256), 256>>>(hs, hstride, gAs + inst * 128, S.ss, ns);
    node_dot_kernel<<<div_up(nd * 32, 256), 256>>>(xd, 128, S.wadall + inst * 128, S.sd, nd);
    gat_fused_kernel<<<div_up(nd * 32, 256), 256>>>(S.ss, S.sd, hs, hstride, rowptr, srcs,
                                                    S.escore, out, nd);
    bias_add_kernel<<<div_up(nd * 32, 256), 256>>>(out, gb + inst * 128, nd);
}

static void edge_tail(const Scratch& S, int pqs, const float* b1, const float* W2,
                      const float* b2, const int* src, const int* dst, int E, int n,
                      float* out)
{
    fill_u32_kernel<<<div_up(n * DIMF, 256), 256>>>(S.emax, NEG_INF_KEY, n * DIMF);
    dim3 grid(1, div_up(E, 128));
    edge_bf3_kernel<<<grid, 256, SMEM_BYTES>>>(S.PQ, pqs, b1, W2, src, dst, S.emax, E);
    finalize_max_b2_kernel<<<div_up(n * DIMF, 256), 256>>>(S.emax, b2, out, n * DIMF);
}

extern "C" void kernel_launch(void* const* d_in, const int* in_sizes, int n_in,
                              void* d_out, int out_size)
{
    const float* x_lego  = (const float*)d_in[0];
    const float* x_point = (const float*)d_in[1];
    const float* tWq = (const float*)d_in[2];
    const float* tbq = (const float*)d_in[3];
    const float* tWk = (const float*)d_in[4];
    const float* tbk = (const float*)d_in[5];
    const float* tWv = (const float*)d_in[6];
    const float* tbv = (const float*)d_in[7];
    const float* tWs = (const float*)d_in[8];
    const float* tbs = (const float*)d_in[9];
    const float* eW1 = (const float*)d_in[10];
    const float* eb1 = (const float*)d_in[11];
    const float* eW2 = (const float*)d_in[12];
    const float* eb2 = (const float*)d_in[13];
    const float* gW  = (const float*)d_in[14];
    const float* gAs = (const float*)d_in[15];
    const float* gAd = (const float*)d_in[16];
    const float* gb  = (const float*)d_in[17];
    const int* ll_src = (const int*)d_in[18];
    const int* ll_dst = (const int*)d_in[19];
    const int* pp_src = (const int*)d_in[20];
    const int* pp_dst = (const int*)d_in[21];
    const int* lp_src = (const int*)d_in[22];
    const int* lp_dst = (const int*)d_in[23];
    const int* pl_src = (const int*)d_in[24];
    const int* pl_dst = (const int*)d_in[25];

    cudaFuncSetAttribute(bf3_gemm_kernel, cudaFuncAttributeMaxDynamicSharedMemorySize,
                         SMEM_BYTES);
    cudaFuncSetAttribute(edge_bf3_kernel, cudaFuncAttributeMaxDynamicSharedMemorySize,
                         SMEM_BYTES);

    Scratch S;
    cudaGetSymbolAddress((void**)&S.xl, g_xl);
    cudaGetSymbolAddress((void**)&S.xp, g_xp);
    cudaGetSymbolAddress((void**)&S.la, g_la);
    cudaGetSymbolAddress((void**)&S.pa, g_pa);
    cudaGetSymbolAddress((void**)&S.ss, g_ss);
    cudaGetSymbolAddress((void**)&S.sd, g_sd);
    cudaGetSymbolAddress((void**)&S.escore, g_escore);
    cudaGetSymbolAddress((void**)&S.QK, g_QK);
    cudaGetSymbolAddress((void**)&S.PQ, g_PQ);
    cudaGetSymbolAddress((void**)&S.emax, g_emax);
    cudaGetSymbolAddress((void**)&S.WcatT, g_WcatT);
    cudaGetSymbolAddress((void**)&S.bcatT, g_bcatT);
    cudaGetSymbolAddress((void**)&S.WcatE, g_WcatE);
    cudaGetSymbolAddress((void**)&S.wadall, g_wadall);
    cudaGetSymbolAddress((void**)&S.hist, g_hist);
    cudaGetSymbolAddress((void**)&S.work, g_work);
    cudaGetSymbolAddress((void**)&S.bsum, g_bsum);
    cudaGetSymbolAddress((void**)&S.sll_s, g_sll_s);
    cudaGetSymbolAddress((void**)&S.spp_s, g_spp_s);
    cudaGetSymbolAddress((void**)&S.spp_d, g_spp_d);
    cudaGetSymbolAddress((void**)&S.slp_s, g_slp_s);
    cudaGetSymbolAddress((void**)&S.spl_s, g_spl_s);
    cudaGetSymbolAddress((void**)&S.rp_ll, g_rp_ll);
    cudaGetSymbolAddress((void**)&S.rp_lp, g_rp_lp);
    cudaGetSymbolAddress((void**)&S.rp_pl, g_rp_pl);

    cudaMemcpyAsync(S.xl, x_lego,  (size_t)N_LEGO * DIMF * sizeof(float),  cudaMemcpyDeviceToDevice);
    cudaMemcpyAsync(S.xp, x_point, (size_t)N_POINT * DIMF * sizeof(float), cudaMemcpyDeviceToDevice);

    concat_trans_kernel<<<div_up(4 * 128 * 640, 256), 256>>>(tWq, tWk, tWv, tWs,
                                                             tbq, tbk, tbv, tbs, gW,
                                                             S.WcatT, S.bcatT);
    concat_edge_kernel<<<div_up(4 * 128 * 1152, 256), 256>>>(eW1, gW, S.WcatE);
    wadall_kernel<<<4, 128>>>(gW, gAd, S.wadall);

    sort_graph(S, ll_src, ll_dst, NE_LL, N_LEGO,  S.sll_s, nullptr, S.rp_ll);
    sort_graph(S, pp_src, pp_dst, NE_PP, N_POINT, S.spp_s, S.spp_d, nullptr);
    sort_graph(S, lp_src, lp_dst, NE_LP, N_POINT, S.slp_s, nullptr, S.rp_lp);
    sort_graph(S, pl_src, pl_dst, NE_PL, N_LEGO,  S.spl_s, nullptr, S.rp_pl);

    float scale = 1.f / sqrtf((float)DIMF);

    for (int layer = 0; layer < 2; layer++) {
        int iA = 2 * layer, iB = 2 * layer + 1;
        int i_lp = 2 * layer, i_pl = 2 * layer + 1;

        // ---- conv A: two merged GEMMs first ----
        sgemm(S.xl, S.WcatT + (size_t)iA * 128 * 640, 640, S.bcatT + iA * 640,
              S.QK, N_LEGO, 640, DIMF);                               // q|k|v|s|hs_lp
        sgemm(S.xp, S.WcatE + (size_t)iA * 128 * 1152, 1152, nullptr,
              S.PQ, N_POINT, 1152, DIMF);                             // R|Q|hs_pl
        // lego_a = trans + gat(point->lego)
        trans_fused_kernel<<<div_up(N_LEGO * 32, 256), 256>>>(
            S.QK, 640, S.rp_ll, S.sll_s, S.escore, S.la, N_LEGO, scale);
        gat_tail(S, S.PQ + 1024, 1152, N_POINT, S.xl, N_LEGO, S.rp_pl, S.spl_s,
                 i_pl, gAs, gb, S.la);
        // point_a = edge + gat(lego->point)
        edge_tail(S, 1152, eb1 + iA * 512, eW2 + (size_t)iA * 512 * DIMF,
                  eb2 + iA * DIMF, S.spp_s, S.spp_d, NE_PP, N_POINT, S.pa);
        gat_tail(S, S.QK + 512, 640, N_LEGO, S.xp, N_POINT, S.rp_lp, S.slp_s,
                 i_lp, gAs, gb, S.pa);

        // ---- conv B: plain widths against the same (strided) weight arrays ----
        sgemm(S.la, S.WcatT + (size_t)iB * 128 * 640, 640, S.bcatT + iB * 640,
              S.QK, N_LEGO, 512, DIMF);
        trans_fused_kernel<<<div_up(N_LEGO * 32, 256), 256>>>(
            S.QK, 512, S.rp_ll, S.sll_s, S.escore, S.xl, N_LEGO, scale);
        sgemm(S.pa, S.WcatE + (size_t)iB * 128 * 1152, 1152, nullptr,
              S.PQ, N_POINT, 1024, DIMF);
        edge_tail(S, 1024, eb1 + iB * 512, eW2 + (size_t)iB * 512 * DIMF,
                  eb2 + iB * DIMF, S.spp_s, S.spp_d, NE_PP, N_POINT, S.xp);
    }

    float* out = (float*)d_out;
    cudaMemcpyAsync(out, S.xl, (size_t)N_LEGO * DIMF * sizeof(float), cudaMemcpyDeviceToDevice);
    cudaMemcpyAsync(out + (size_t)N_LEGO * DIMF, S.xp, (size_t)N_POINT * DIMF * sizeof(float),
                    cudaMemcpyDeviceToDevice);
}

// round 14
// speedup vs baseline: 1.0423x; 1.0423x over previous
#include <cuda_runtime.h>
#include <math.h>
#include <stdint.h>

#define DIMF 128
#define N_LEGO 50000
#define N_POINT 100000
#define NE_LL 500000
#define NE_PP 400000
#define NE_LP 500000
#define NE_PL 500000
#define NEG_INF_KEY 0x007FFFFFu
#define SCAN_B 512

// ---------------- scratch ----------------
__device__ float    g_xl[N_LEGO * DIMF];
__device__ float    g_xp[N_POINT * DIMF];
__device__ float    g_la[N_LEGO * DIMF];
__device__ float    g_pa[N_POINT * DIMF];
__device__ float    g_hs[N_POINT * DIMF];
__device__ float    g_ss[N_POINT];
__device__ float    g_sd[N_POINT];
__device__ float    g_escore[NE_LL];
__device__ float    g_PQ[(size_t)N_POINT * 1024];
__device__ unsigned g_emax[N_POINT * DIMF];
__device__ float    g_WcatT[4 * 128 * 512];
__device__ float    g_bcatT[4 * 512];
__device__ float    g_WcatE[4 * 128 * 1024];
__device__ float    g_wadall[4 * 128];
// sort scratch + sorted edge lists + CSR rowptrs
__device__ int g_hist[N_POINT], g_work[N_POINT], g_bsum[SCAN_B];
__device__ int g_sll_s[NE_LL];
__device__ int g_spp_s[NE_PP], g_spp_d[NE_PP];
__device__ int g_slp_s[NE_LP];
__device__ int g_spl_s[NE_PL];
__device__ int g_rp_ll[N_LEGO + 1], g_rp_lp[N_POINT + 1], g_rp_pl[N_LEGO + 1];

// ---------------- helpers ----------------
__device__ __forceinline__ unsigned fkey(float f) {
    unsigned u = __float_as_uint(f);
    return (u & 0x80000000u) ? ~u : (u | 0x80000000u);
}
__device__ __forceinline__ float fdecode(unsigned kk) {
    unsigned u = (kk & 0x80000000u) ? (kk ^ 0x80000000u) : ~kk;
    return __uint_as_float(u);
}
__device__ __forceinline__ uint2 bfsplit2(float v0, float v1) {
    uint32_t h, m;
    asm("cvt.rn.bf16x2.f32 %0, %1, %2;" : "=r"(h) : "f"(v1), "f"(v0));
    float h0 = __uint_as_float(h << 16);
    float h1 = __uint_as_float(h & 0xffff0000u);
    asm("cvt.rn.bf16x2.f32 %0, %1, %2;" : "=r"(m) : "f"(v1 - h1), "f"(v0 - h0));
    return make_uint2(h, m);
}

// ---------------- GEMM (round-7/8 WIN, unchanged) ----------------
#define AHS 20
#define BHS 136
#define AH_OFF 0
#define AM_OFF 2560
#define BH_OFF 5120
#define BM_OFF 7296
#define STAGE_U 9472
#define SMEM_BYTES (2 * STAGE_U * 4)

#define MMA_BF16(accv, a0, a1, a2, a3, b0, b1)                                     \
    asm("mma.sync.aligned.m16n8k16.row.col.f32.bf16.bf16.f32 "                     \
        "{%0,%1,%2,%3}, {%4,%5,%6,%7}, {%8,%9}, {%0,%1,%2,%3};"                    \
        : "+f"(accv[0]), "+f"(accv[1]), "+f"(accv[2]), "+f"(accv[3])               \
        : "r"(a0), "r"(a1), "r"(a2), "r"(a3), "r"(b0), "r"(b1))

#define BF_COMPUTE(sb)                                                             \
    {                                                                              \
        _Pragma("unroll")                                                          \
        for (int kc = 0; kc < 2; kc++) {                                           \
            uint32_t ah[2][4], am[2][4];                                           \
            _Pragma("unroll")                                                      \
            for (int mt = 0; mt < 2; mt++) {                                       \
                int r0 = wm + mt * 16 + g;                                         \
                int o0 = r0 * AHS + kc * 8 + t, o1 = (r0 + 8) * AHS + kc * 8 + t;  \
                ah[mt][0] = (sb)[AH_OFF + o0];     ah[mt][1] = (sb)[AH_OFF + o1];  \
                ah[mt][2] = (sb)[AH_OFF + o0 + 4]; ah[mt][3] = (sb)[AH_OFF + o1 + 4]; \
                am[mt][0] = (sb)[AM_OFF + o0];     am[mt][1] = (sb)[AM_OFF + o1];  \
                am[mt][2] = (sb)[AM_OFF + o0 + 4]; am[mt][3] = (sb)[AM_OFF + o1 + 4]; \
            }                                                                      \
            _Pragma("unroll")                                                      \
            for (int nt = 0; nt < 8; nt++) {                                       \
                int nn = wn + nt * 8 + g;                                          \
                int p0 = (kc * 8 + t) * BHS + nn, p1 = (kc * 8 + t + 4) * BHS + nn;\
                uint32_t b0h = (sb)[BH_OFF + p0], b1h = (sb)[BH_OFF + p1];         \
                uint32_t b0m = (sb)[BM_OFF + p0], b1m = (sb)[BM_OFF + p1];         \
                _Pragma("unroll")                                                  \
                for (int mt = 0; mt < 2; mt++) {                                   \
                    MMA_BF16(acc[mt][nt], am[mt][0], am[mt][1], am[mt][2],         \
                             am[mt][3], b0h, b1h);                                 \
                    MMA_BF16(acc[mt][nt], ah[mt][0], ah[mt][1], ah[mt][2],         \
                             ah[mt][3], b0m, b1m);                                 \
                    MMA_BF16(acc[mt][nt], ah[mt][0], ah[mt][1], ah[mt][2],         \
                             ah[mt][3], b0h, b1h);                                 \
                }                                                                  \
            }                                                                      \
        }                                                                          \
    }

#define STS_A4(sb, row, c4, v4)                                                    \
    {                                                                              \
        int k2c = (c4) >> 1;                                                       \
        uint2 p01 = bfsplit2((v4).x, (v4).y);                                      \
        uint2 p23 = bfsplit2((v4).z, (v4).w);                                      \
        *(uint2*)((sb) + AH_OFF + (row) * AHS + k2c) = make_uint2(p01.x, p23.x);   \
        *(uint2*)((sb) + AM_OFF + (row) * AHS + k2c) = make_uint2(p01.y, p23.y);   \
    }
#define STS_B4(sb, k2, c4, v0, v1)                                                 \
    {                                                                              \
        uint2 q0 = bfsplit2((v0).x, (v1).x);                                       \
        uint2 q1 = bfsplit2((v0).y, (v1).y);                                       \
        uint2 q2 = bfsplit2((v0).z, (v1).z);                                       \
        uint2 q3 = bfsplit2((v0).w, (v1).w);                                       \
        *(uint4*)((sb) + BH_OFF + (k2) * BHS + (c4)) = make_uint4(q0.x, q1.x, q2.x, q3.x); \
        *(uint4*)((sb) + BM_OFF + (k2) * BHS + (c4)) = make_uint4(q0.y, q1.y, q2.y, q3.y); \
    }

__global__ __launch_bounds__(256, 2) void bf3_gemm_kernel(
    const float* __restrict__ A, const float* __restrict__ B,
    const float* __restrict__ bias, float* __restrict__ C,
    int M, int N, int K)
{
    extern __shared__ uint32_t smu[];
    const int tid = threadIdx.x;
    const int warp = tid >> 5, lane = tid & 31;
    const int g = lane >> 2, t = lane & 3;
    const int warp_m = warp & 3, warp_n = warp >> 2;
    const int m_base = blockIdx.y * 128, n_base = blockIdx.x * 128;
    const int wm = warp_m * 32, wn = warp_n * 64;
    const int a_row = tid >> 3, a_c4 = (tid & 7) * 4;
    const int b_k2 = tid >> 5, b_c4 = (tid & 31) * 4;

    float acc[2][8][4];
#pragma unroll
    for (int i = 0; i < 2; i++)
#pragma unroll
        for (int j = 0; j < 8; j++)
#pragma unroll
            for (int c = 0; c < 4; c++) acc[i][j][c] = 0.f;

    float4 av[4], bv0[2], bv1[2];
    const float4 f4z = make_float4(0.f, 0.f, 0.f, 0.f);

#define GEN_LDG(kt)                                                                \
    {                                                                              \
        _Pragma("unroll")                                                          \
        for (int i = 0; i < 4; i++) {                                              \
            int row = a_row + i * 32, gr = m_base + row;                           \
            av[i] = (gr < M) ? *(const float4*)(A + (size_t)gr * K + (kt) + a_c4)  \
                             : f4z;                                                \
        }                                                                          \
        _Pragma("unroll")                                                          \
        for (int i = 0; i < 2; i++) {                                              \
            int k2 = b_k2 + i * 8;                                                 \
            bv0[i] = *(const float4*)(B + (size_t)((kt) + 2 * k2) * N + n_base + b_c4);     \
            bv1[i] = *(const float4*)(B + (size_t)((kt) + 2 * k2 + 1) * N + n_base + b_c4); \
        }                                                                          \
    }
#define GEN_STS(st)                                                                \
    {                                                                              \
        uint32_t* sb = smu + (st) * STAGE_U;                                       \
        _Pragma("unroll")                                                          \
        for (int i = 0; i < 4; i++) STS_A4(sb, a_row + i * 32, a_c4, av[i]);       \
        _Pragma("unroll")                                                          \
        for (int i = 0; i < 2; i++) STS_B4(sb, b_k2 + i * 8, b_c4, bv0[i], bv1[i]);\
    }

    GEN_LDG(0);
    int stage = 0;
    for (int kt = 0; kt < K; kt += 32, stage ^= 1) {
        GEN_STS(stage);
        __syncthreads();
        if (kt + 32 < K) GEN_LDG(kt + 32);
        const uint32_t* sb = smu + stage * STAGE_U;
        BF_COMPUTE(sb);
    }

#pragma unroll
    for (int mt = 0; mt < 2; mt++) {
        int r0 = m_base + wm + mt * 16 + g, r1 = r0 + 8;
#pragma unroll
        for (int nt = 0; nt < 8; nt++) {
            int c = n_base + wn + nt * 8 + 2 * t;
            float b0 = 0.f, b1 = 0.f;
            if (bias) { b0 = bias[c]; b1 = bias[c + 1]; }
            if (r0 < M) *(float2*)(C + (size_t)r0 * N + c) =
                make_float2(acc[mt][nt][0] + b0, acc[mt][nt][1] + b1);
            if (r1 < M) *(float2*)(C + (size_t)r1 * N + c) =
                make_float2(acc[mt][nt][2] + b0, acc[mt][nt][3] + b1);
        }
    }
}

// ---------------- fused EdgeConv MLP2 + segment-max (round-8 WIN, unchanged) ----------------
__global__ __launch_bounds__(256, 2) void edge_bf3_kernel(
    const float* __restrict__ PQ, const float* __restrict__ b1,
    const float* __restrict__ W2,
    const int* __restrict__ src, const int* __restrict__ dst,
    unsigned* __restrict__ emax, int E)
{
    extern __shared__ uint32_t smu[];
    __shared__ int se[128], de[128];
    const int tid = threadIdx.x;
    const int warp = tid >> 5, lane = tid & 31;
    const int g = lane >> 2, t = lane & 3;
    const int warp_m = warp & 3, warp_n = warp >> 2;
    const int e_base = blockIdx.y * 128;
    const int wm = warp_m * 32, wn = warp_n * 64;
    const int a_row = tid >> 3, a_c4 = (tid & 7) * 4;
    const int b_k2 = tid >> 5, b_c4 = (tid & 31) * 4;

    if (tid < 128) {
        int e = e_base + tid;
        bool ok = (e < E);
        se[tid] = ok ? src[e] : 0;
        de[tid] = ok ? dst[e] : 0;
    }
    __syncthreads();

    float acc[2][8][4];
#pragma unroll
    for (int i = 0; i < 2; i++)
#pragma unroll
        for (int j = 0; j < 8; j++)
#pragma unroll
            for (int c = 0; c < 4; c++) acc[i][j][c] = 0.f;

    float4 bv0[2], bv1[2];

#define EB_LDG(kt)                                                                 \
    {                                                                              \
        _Pragma("unroll")                                                          \
        for (int i = 0; i < 2; i++) {                                              \
            int k2 = b_k2 + i * 8;                                                 \
            bv0[i] = *(const float4*)(W2 + (size_t)((kt) + 2 * k2) * 128 + b_c4);     \
            bv1[i] = *(const float4*)(W2 + (size_t)((kt) + 2 * k2 + 1) * 128 + b_c4); \
        }                                                                          \
    }
#define EB_B_STS(st)                                                               \
    {                                                                              \
        uint32_t* sb = smu + (st) * STAGE_U;                                       \
        _Pragma("unroll")                                                          \
        for (int i = 0; i < 2; i++) STS_B4(sb, b_k2 + i * 8, b_c4, bv0[i], bv1[i]);\
    }
#define EB_A_STS(kt, st)                                                           \
    {                                                                              \
        uint32_t* sb = smu + (st) * STAGE_U;                                       \
        float4 bb = *(const float4*)(b1 + (kt) + a_c4);                            \
        _Pragma("unroll")                                                          \
        for (int i = 0; i < 4; i++) {                                              \
            int row = a_row + i * 32;                                              \
            size_t dof = (size_t)de[row] * 1024, sof = (size_t)se[row] * 1024 + 512; \
            float4 rv = *(const float4*)(PQ + dof + (kt) + a_c4);                  \
            float4 qv = *(const float4*)(PQ + sof + (kt) + a_c4);                  \
            float4 h;                                                              \
            h.x = fmaxf(rv.x + qv.x + bb.x, 0.f);                                  \
            h.y = fmaxf(rv.y + qv.y + bb.y, 0.f);                                  \
            h.z = fmaxf(rv.z + qv.z + bb.z, 0.f);                                  \
            h.w = fmaxf(rv.w + qv.w + bb.w, 0.f);                                  \
            STS_A4(sb, row, a_c4, h);                                              \
        }                                                                          \
    }

    EB_A_STS(0, 0);
    EB_LDG(0);
    int stage = 0;
    for (int kt = 0; kt < 512; kt += 32, stage ^= 1) {
        EB_B_STS(stage);
        __syncthreads();
        if (kt + 32 < 512) EB_LDG(kt + 32);
        const uint32_t* sb = smu + stage * STAGE_U;
        BF_COMPUTE(sb);
        if (kt + 32 < 512) EB_A_STS(kt + 32, stage ^ 1);
    }

#pragma unroll
    for (int mt = 0; mt < 2; mt++) {
        int r0 = wm + mt * 16 + g, r1 = r0 + 8;
        int e0 = e_base + r0, e1 = e_base + r1;
        int d0 = de[r0], d1 = de[r1];
#pragma unroll
        for (int nt = 0; nt < 8; nt++) {
            int c = wn + nt * 8 + 2 * t;
            if (e0 < E) {
                atomicMax(emax + (size_t)d0 * DIMF + c,     fkey(acc[mt][nt][0]));
                atomicMax(emax + (size_t)d0 * DIMF + c + 1, fkey(acc[mt][nt][1]));
            }
            if (e1 < E) {
                atomicMax(emax + (size_t)d1 * DIMF + c,     fkey(acc[mt][nt][2]));
                atomicMax(emax + (size_t)d1 * DIMF + c + 1, fkey(acc[mt][nt][3]));
            }
        }
    }
}

// ---------------- CSR-fused attention kernels ----------------
__global__ void trans_fused_kernel(
    const float* __restrict__ qkvs, const int* __restrict__ rowptr,
    const int* __restrict__ srcs, float* __restrict__ escore,
    float* __restrict__ out, int n, float scale)
{
    int idx = blockIdx.x * blockDim.x + threadIdx.x;
    int d = idx >> 5, lane = idx & 31;
    if (d >= n) return;
    int beg = rowptr[d], end = rowptr[d + 1];
    if (beg == end) return;
    float4 q = *(const float4*)(qkvs + (size_t)d * 512 + lane * 4);
    float m = -INFINITY;
    for (int e = beg; e < end; e++) {
        int s0 = srcs[e];
        float4 kv = *(const float4*)(qkvs + (size_t)s0 * 512 + 128 + lane * 4);
        float s = q.x * kv.x + q.y * kv.y + q.z * kv.z + q.w * kv.w;
#pragma unroll
        for (int o = 16; o; o >>= 1) s += __shfl_xor_sync(0xffffffffu, s, o);
        s *= scale;
        if (lane == 0) escore[e] = s;
        m = fmaxf(m, s);
    }
    __syncwarp();
    float4 acc = make_float4(0.f, 0.f, 0.f, 0.f);
    float dsum = 0.f;
    for (int e = beg; e < end; e++) {
        float ex = expf(escore[e] - m);
        dsum += ex;
        int s0 = srcs[e];
        float4 vv = *(const float4*)(qkvs + (size_t)s0 * 512 + 256 + lane * 4);
        acc.x += ex * vv.x; acc.y += ex * vv.y;
        acc.z += ex * vv.z; acc.w += ex * vv.w;
    }
    float inv = 1.f / (dsum + 1e-16f);
    float* op = out + (size_t)d * DIMF + lane * 4;
    float4 o = *(float4*)op;
    o.x += acc.x * inv; o.y += acc.y * inv;
    o.z += acc.z * inv; o.w += acc.w * inv;
    *(float4*)op = o;
}

// gat with folded bias: out[d] += gb (always) + softmax-agg (if edges)
__global__ void gat_fused_kernel(
    const float* __restrict__ ss, const float* __restrict__ sd,
    const float* __restrict__ hs, const int* __restrict__ rowptr,
    const int* __restrict__ srcs, float* __restrict__ escore,
    const float* __restrict__ gb, float* __restrict__ out, int n)
{
    int idx = blockIdx.x * blockDim.x + threadIdx.x;
    int d = idx >> 5, lane = idx & 31;
    if (d >= n) return;
    float* op = out + (size_t)d * DIMF + lane * 4;
    float4 o = *(float4*)op;
    float4 bv = *(const float4*)(gb + lane * 4);
    o.x += bv.x; o.y += bv.y; o.z += bv.z; o.w += bv.w;
    int beg = rowptr[d], end = rowptr[d + 1];
    if (beg < end) {
        float sdd = sd[d];
        float m = -INFINITY;
        for (int e = beg + lane; e < end; e += 32) {
            float s = ss[srcs[e]] + sdd;
            s = (s > 0.f) ? s : 0.2f * s;
            escore[e] = s;
            m = fmaxf(m, s);
        }
#pragma unroll
        for (int oo = 16; oo; oo >>= 1) m = fmaxf(m, __shfl_xor_sync(0xffffffffu, m, oo));
        __syncwarp();
        float4 acc = make_float4(0.f, 0.f, 0.f, 0.f);
        float dsum = 0.f;
        for (int e = beg; e < end; e++) {
            float ex = expf(escore[e] - m);
            dsum += ex;
            int s0 = srcs[e];
            float4 hv = *(const float4*)(hs + (size_t)s0 * DIMF + lane * 4);
            acc.x += ex * hv.x; acc.y += ex * hv.y;
            acc.z += ex * hv.z; acc.w += ex * hv.w;
        }
        float inv = 1.f / (dsum + 1e-16f);
        o.x += acc.x * inv; o.y += acc.y * inv;
        o.z += acc.z * inv; o.w += acc.w * inv;
    }
    *(float4*)op = o;
}

// ---------------- one-time weight prep ----------------
__global__ void concat_trans_kernel(const float* Wq, const float* Wk, const float* Wv,
                                    const float* Ws, const float* bq, const float* bk,
                                    const float* bv, const float* bs,
                                    float* Wcat, float* bcat)
{
    int i = blockIdx.x * blockDim.x + threadIdx.x;
    if (i >= 4 * 128 * 512) return;
    int inst = i >> 16, r = (i >> 9) & 127, j = i & 511;
    int sel = j >> 7, jj = j & 127;
    const float* W = sel == 0 ? Wq : sel == 1 ? Wk : sel == 2 ? Wv : Ws;
    Wcat[i] = W[((size_t)inst * 128 + r) * 128 + jj];
    if (r == 0) {
        const float* bb = sel == 0 ? bq : sel == 1 ? bk : sel == 2 ? bv : bs;
        bcat[inst * 512 + j] = bb[inst * 128 + jj];
    }
}
__global__ void concat_edge_kernel(const float* W1, float* Wcat)
{
    int i = blockIdx.x * blockDim.x + threadIdx.x;
    if (i >= 4 * 128 * 1024) return;
    int inst = i >> 17, r = (i >> 10) & 127, j = i & 1023;
    const float* Wi = W1 + (size_t)inst * 256 * 512;
    if (j < 512) Wcat[i] = Wi[(size_t)r * 512 + j] - Wi[(size_t)(128 + r) * 512 + j];
    else         Wcat[i] = Wi[(size_t)(128 + r) * 512 + (j - 512)];
}
__global__ void wadall_kernel(const float* __restrict__ gW, const float* __restrict__ gAd,
                              float* __restrict__ wad)
{
    int b = blockIdx.x, j = threadIdx.x;
    float s = 0.f;
    for (int kk = 0; kk < 128; kk++)
        s += gW[((size_t)b * 128 + j) * 128 + kk] * gAd[b * 128 + kk];
    wad[b * 128 + j] = s;
}

// ---------------- counting sort by dst + rowptr ----------------
__global__ void fill_i32_kernel(int* p, int val, int n) {
    int i = blockIdx.x * blockDim.x + threadIdx.x;
    if (i < n) p[i] = val;
}
__global__ void count_kernel(const int* __restrict__ dst, int* __restrict__ hist, int E) {
    int e = blockIdx.x * blockDim.x + threadIdx.x;
    if (e < E) atomicAdd(hist + dst[e], 1);
}
__global__ void scan1_kernel(const int* __restrict__ hist, int* __restrict__ off,
                             int* __restrict__ bsum, int n) {
    __shared__ int sh[SCAN_B];
    int tid = threadIdx.x, i = blockIdx.x * SCAN_B + tid;
    int v = (i < n) ? hist[i] : 0;
    sh[tid] = v; __syncthreads();
    for (int d = 1; d < SCAN_B; d <<= 1) {
        int t2 = (tid >= d) ? sh[tid - d] : 0;
        __syncthreads(); sh[tid] += t2; __syncthreads();
    }
    if (i < n) off[i] = sh[tid] - v;
    if (tid == SCAN_B - 1) bsum[blockIdx.x] = sh[tid];
}
__global__ void scan2_kernel(int* __restrict__ bsum, int nb) {
    __shared__ int sh[SCAN_B];
    int tid = threadIdx.x;
    int v = (tid < nb) ? bsum[tid] : 0;
    sh[tid] = v; __syncthreads();
    for (int d = 1; d < SCAN_B; d <<= 1) {
        int t2 = (tid >= d) ? sh[tid - d] : 0;
        __syncthreads(); sh[tid] += t2; __syncthreads();
    }
    if (tid < nb) bsum[tid] = sh[tid] - v;
}
__global__ void scan3_kernel(const int* __restrict__ off, const int* __restrict__ bsum,
                             int* __restrict__ work, int* __restrict__ rowptr,
                             int n, int E) {
    int i = blockIdx.x * blockDim.x + threadIdx.x;
    if (i < n) {
        int v = off[i] + bsum[i / SCAN_B];
        work[i] = v;
        if (rowptr) rowptr[i] = v;
    }
    if (i == 0 && rowptr) rowptr[n] = E;
}
__global__ void scatter_kernel(const int* __restrict__ src, const int* __restrict__ dst,
                               int* __restrict__ work,
                               int* __restrict__ osrc, int* __restrict__ odst, int E) {
    int e = blockIdx.x * blockDim.x + threadIdx.x;
    if (e >= E) return;
    int d = dst[e];
    int pos = atomicAdd(work + d, 1);
    osrc[pos] = src[e];
    if (odst) odst[pos] = d;
}

// ---------------- small glue kernels ----------------
__global__ void fill_u32_kernel(unsigned* p, unsigned val, int n) {
    int i = blockIdx.x * blockDim.x + threadIdx.x;
    if (i < n) p[i] = val;
}
__global__ void copy_skip_kernel(const float* __restrict__ qkvs, float* __restrict__ out, int n) {
    int i = blockIdx.x * blockDim.x + threadIdx.x;
    if (i >= n * 32) return;
    int row = i >> 5, f = (i & 31) * 4;
    *(float4*)(out + (size_t)row * DIMF + f) =
        *(const float4*)(qkvs + (size_t)row * 512 + 384 + f);
}
__global__ void node_dot_kernel(const float* __restrict__ h, const float* __restrict__ avec,
                                float* __restrict__ out, int n)
{
    int idx = blockIdx.x * blockDim.x + threadIdx.x;
    int i = idx >> 5, lane = idx & 31;
    if (i >= n) return;
    float4 hv = *(const float4*)(h + (size_t)i * DIMF + lane * 4);
    float4 av = *(const float4*)(avec + lane * 4);
    float s = hv.x * av.x + hv.y * av.y + hv.z * av.z + hv.w * av.w;
#pragma unroll
    for (int o = 16; o; o >>= 1) s += __shfl_xor_sync(0xffffffffu, s, o);
    if (lane == 0) out[i] = s;
}
__global__ void finalize_max_b2_kernel(const unsigned* __restrict__ emax,
                                       const float* __restrict__ b2,
                                       float* __restrict__ out, int total) {
    int i = blockIdx.x * blockDim.x + threadIdx.x;
    if (i >= total) return;
    float v = fdecode(emax[i]);
    out[i] = isfinite(v) ? v + b2[i & (DIMF - 1)] : 0.f;
}

// ---------------- host orchestration ----------------
static inline int div_up(int a, int b) { return (a + b - 1) / b; }

struct Scratch {
    float *xl, *xp, *la, *pa, *hs, *ss, *sd, *escore, *PQ;
    float *WcatT, *bcatT, *WcatE, *wadall;
    unsigned *emax;
    int *hist, *work, *bsum;
    int *sll_s, *spp_s, *spp_d, *slp_s, *spl_s;
    int *rp_ll, *rp_lp, *rp_pl;
};

static void sort_graph(const Scratch& S, const int* src, const int* dst, int E, int n,
                       int* osrc, int* odst, int* rowptr)
{
    fill_i32_kernel<<<div_up(n, 256), 256>>>(S.hist, 0, n);
    count_kernel<<<div_up(E, 256), 256>>>(dst, S.hist, E);
    int nb = div_up(n, SCAN_B);
    scan1_kernel<<<nb, SCAN_B>>>(S.hist, S.work, S.bsum, n);
    scan2_kernel<<<1, SCAN_B>>>(S.bsum, nb);
    scan3_kernel<<<div_up(n, 256), 256>>>(S.work, S.bsum, S.hist, rowptr, n, E);
    scatter_kernel<<<div_up(E, 256), 256>>>(src, dst, S.hist, osrc, odst, E);
}

static void sgemm(const float* A, const float* B, const float* bias, float* C,
                  int M, int N, int K) {
    dim3 grid(N / 128, div_up(M, 128));
    bf3_gemm_kernel<<<grid, 256, SMEM_BYTES>>>(A, B, bias, C, M, N, K);
}

static void run_trans(const Scratch& S, const float* x, int n, int inst,
                      const int* rowptr, const int* srcs, float* out)
{
    sgemm(x, S.WcatT + (size_t)inst * 128 * 512, S.bcatT + inst * 512, S.PQ, n, 512, DIMF);
    copy_skip_kernel<<<div_up(n * 32, 256), 256>>>(S.PQ, out, n);
    float scale = 1.f / sqrtf((float)DIMF);
    trans_fused_kernel<<<div_up(n * 32, 256), 256>>>(S.PQ, rowptr, srcs, S.escore,
                                                     out, n, scale);
}

static void run_gat(const Scratch& S, const float* xs, int ns, const float* xd, int nd,
                    const int* rowptr, const int* srcs, int inst,
                    const float* W, const float* a_src, const float* gb, float* out)
{
    sgemm(xs, W, nullptr, S.hs, ns, DIMF, DIMF);
    node_dot_kernel<<<div_up(ns * 32, 256), 256>>>(S.hs, a_src, S.ss, ns);
    node_dot_kernel<<<div_up(nd * 32, 256), 256>>>(xd, S.wadall + inst * 128, S.sd, nd);
    gat_fused_kernel<<<div_up(nd * 32, 256), 256>>>(S.ss, S.sd, S.hs, rowptr, srcs,
                                                    S.escore, gb, out, nd);
}

static void run_edge(const Scratch& S, const float* x, int n, int inst,
                     const int* src, const int* dst, int E,
                     const float* b1, const float* W2, const float* b2, float* out)
{
    sgemm(x, S.WcatE + (size_t)inst * 128 * 1024, nullptr, S.PQ, n, 1024, DIMF);
    fill_u32_kernel<<<div_up(n * DIMF, 256), 256>>>(S.emax, NEG_INF_KEY, n * DIMF);
    dim3 grid(1, div_up(E, 128));
    edge_bf3_kernel<<<grid, 256, SMEM_BYTES>>>(S.PQ, b1, W2, src, dst, S.emax, E);
    finalize_max_b2_kernel<<<div_up(n * DIMF, 256), 256>>>(S.emax, b2, out, n * DIMF);
}

extern "C" void kernel_launch(void* const* d_in, const int* in_sizes, int n_in,
                              void* d_out, int out_size)
{
    const float* x_lego  = (const float*)d_in[0];
    const float* x_point = (const float*)d_in[1];
    const float* tWq = (const float*)d_in[2];
    const float* tbq = (const float*)d_in[3];
    const float* tWk = (const float*)d_in[4];
    const float* tbk = (const float*)d_in[5];
    const float* tWv = (const float*)d_in[6];
    const float* tbv = (const float*)d_in[7];
    const float* tWs = (const float*)d_in[8];
    const float* tbs = (const float*)d_in[9];
    const float* eW1 = (const float*)d_in[10];
    const float* eb1 = (const float*)d_in[11];
    const float* eW2 = (const float*)d_in[12];
    const float* eb2 = (const float*)d_in[13];
    const float* gW  = (const float*)d_in[14];
    const float* gAs = (const float*)d_in[15];
    const float* gAd = (const float*)d_in[16];
    const float* gb  = (const float*)d_in[17];
    const int* ll_src = (const int*)d_in[18];
    const int* ll_dst = (const int*)d_in[19];
    const int* pp_src = (const int*)d_in[20];
    const int* pp_dst = (const int*)d_in[21];
    const int* lp_src = (const int*)d_in[22];
    const int* lp_dst = (const int*)d_in[23];
    const int* pl_src = (const int*)d_in[24];
    const int* pl_dst = (const int*)d_in[25];

    cudaFuncSetAttribute(bf3_gemm_kernel, cudaFuncAttributeMaxDynamicSharedMemorySize,
                         SMEM_BYTES);
    cudaFuncSetAttribute(edge_bf3_kernel, cudaFuncAttributeMaxDynamicSharedMemorySize,
                         SMEM_BYTES);

    Scratch S;
    cudaGetSymbolAddress((void**)&S.xl, g_xl);
    cudaGetSymbolAddress((void**)&S.xp, g_xp);
    cudaGetSymbolAddress((void**)&S.la, g_la);
    cudaGetSymbolAddress((void**)&S.pa, g_pa);
    cudaGetSymbolAddress((void**)&S.hs, g_hs);
    cudaGetSymbolAddress((void**)&S.ss, g_ss);
    cudaGetSymbolAddress((void**)&S.sd, g_sd);
    cudaGetSymbolAddress((void**)&S.escore, g_escore);
    cudaGetSymbolAddress((void**)&S.PQ, g_PQ);
    cudaGetSymbolAddress((void**)&S.emax, g_emax);
    cudaGetSymbolAddress((void**)&S.WcatT, g_WcatT);
    cudaGetSymbolAddress((void**)&S.bcatT, g_bcatT);
    cudaGetSymbolAddress((void**)&S.WcatE, g_WcatE);
    cudaGetSymbolAddress((void**)&S.wadall, g_wadall);
    cudaGetSymbolAddress((void**)&S.hist, g_hist);
    cudaGetSymbolAddress((void**)&S.work, g_work);
    cudaGetSymbolAddress((void**)&S.bsum, g_bsum);
    cudaGetSymbolAddress((void**)&S.sll_s, g_sll_s);
    cudaGetSymbolAddress((void**)&S.spp_s, g_spp_s);
    cudaGetSymbolAddress((void**)&S.spp_d, g_spp_d);
    cudaGetSymbolAddress((void**)&S.slp_s, g_slp_s);
    cudaGetSymbolAddress((void**)&S.spl_s, g_spl_s);
    cudaGetSymbolAddress((void**)&S.rp_ll, g_rp_ll);
    cudaGetSymbolAddress((void**)&S.rp_lp, g_rp_lp);
    cudaGetSymbolAddress((void**)&S.rp_pl, g_rp_pl);

    cudaMemcpyAsync(S.xl, x_lego,  (size_t)N_LEGO * DIMF * sizeof(float),  cudaMemcpyDeviceToDevice);
    cudaMemcpyAsync(S.xp, x_point, (size_t)N_POINT * DIMF * sizeof(float), cudaMemcpyDeviceToDevice);

    concat_trans_kernel<<<div_up(4 * 128 * 512, 256), 256>>>(tWq, tWk, tWv, tWs,
                                                             tbq, tbk, tbv, tbs,
                                                             S.WcatT, S.bcatT);
    concat_edge_kernel<<<div_up(4 * 128 * 1024, 256), 256>>>(eW1, S.WcatE);
    wadall_kernel<<<4, 128>>>(gW, gAd, S.wadall);

    sort_graph(S, ll_src, ll_dst, NE_LL, N_LEGO,  S.sll_s, nullptr, S.rp_ll);
    sort_graph(S, pp_src, pp_dst, NE_PP, N_POINT, S.spp_s, S.spp_d, nullptr);
    sort_graph(S, lp_src, lp_dst, NE_LP, N_POINT, S.slp_s, nullptr, S.rp_lp);
    sort_graph(S, pl_src, pl_dst, NE_PL, N_LEGO,  S.spl_s, nullptr, S.rp_pl);

    for (int layer = 0; layer < 2; layer++) {
        int iA = 2 * layer, iB = 2 * layer + 1;
        int i_lp = 2 * layer, i_pl = 2 * layer + 1;

        run_trans(S, S.xl, N_LEGO, iA, S.rp_ll, S.sll_s, S.la);
        run_gat(S, S.xp, N_POINT, S.xl, N_LEGO, S.rp_pl, S.spl_s, i_pl,
                gW + i_pl * DIMF * DIMF, gAs + i_pl * DIMF, gb + i_pl * DIMF, S.la);

        run_edge(S, S.xp, N_POINT, iA, S.spp_s, S.spp_d, NE_PP,
                 eb1 + iA * 512, eW2 + (size_t)iA * 512 * DIMF, eb2 + iA * DIMF, S.pa);
        run_gat(S, S.xl, N_LEGO, S.xp, N_POINT, S.rp_lp, S.slp_s, i_lp,
                gW + i_lp * DIMF * DIMF, gAs + i_lp * DIMF, gb + i_lp * DIMF, S.pa);

        run_trans(S, S.la, N_LEGO, iB, S.rp_ll, S.sll_s, S.xl);
        run_edge(S, S.pa, N_POINT, iB, S.spp_s, S.spp_d, NE_PP,
                 eb1 + iB * 512, eW2 + (size_t)iB * 512 * DIMF, eb2 + iB * DIMF, S.xp);
    }

    float* out = (float*)d_out;
    cudaMemcpyAsync(out, S.xl, (size_t)N_LEGO * DIMF * sizeof(float), cudaMemcpyDeviceToDevice);
    cudaMemcpyAsync(out + (size_t)N_LEGO * DIMF, S.xp, (size_t)N_POINT * DIMF * sizeof(float),
                    cudaMemcpyDeviceToDevice);
}

// round 15
// speedup vs baseline: 1.0643x; 1.0211x over previous
#include <cuda_runtime.h>
#include <math.h>
#include <stdint.h>

#define DIMF 128
#define N_LEGO 50000
#define N_POINT 100000
#define NE_LL 500000
#define NE_PP 400000
#define NE_LP 500000
#define NE_PL 500000
#define NEG_INF_KEY 0x007FFFFFu
#define SCAN_B 1024
// concatenated node/edge spaces for the batched sort
#define O_LL 0
#define O_PP N_LEGO
#define O_LP (N_LEGO + N_POINT)
#define O_PL (N_LEGO + 2 * N_POINT)
#define NT_NODES (2 * N_LEGO + 2 * N_POINT)        // 300000
#define F_LL 0
#define F_PP NE_LL
#define F_LP (NE_LL + NE_PP)
#define F_PL (NE_LL + NE_PP + NE_LP)
#define E_TOT (NE_LL + NE_PP + NE_LP + NE_PL)      // 1.9M

// ---------------- scratch ----------------
__device__ float    g_xl[N_LEGO * DIMF];
__device__ float    g_xp[N_POINT * DIMF];
__device__ float    g_la[N_LEGO * DIMF];
__device__ float    g_pa[N_POINT * DIMF];
__device__ float    g_hs[N_POINT * DIMF];
__device__ float    g_ss[N_POINT];
__device__ float    g_sd[N_POINT];
__device__ float    g_escore[NE_LL];
__device__ float    g_PQ[(size_t)N_POINT * 1024];
__device__ unsigned g_emax[N_POINT * DIMF];
__device__ float    g_WcatT[4 * 128 * 512];
__device__ float    g_bcatT[4 * 512];
__device__ float    g_WcatE[4 * 128 * 1024];
__device__ float    g_wadall[4 * 128];
// batched sort scratch + sorted edge lists + CSR rowptrs
__device__ int g_hist4[NT_NODES], g_work4[NT_NODES], g_bsum[SCAN_B];
__device__ int g_sll_s[NE_LL];
__device__ int g_spp_s[NE_PP], g_spp_d[NE_PP];
__device__ int g_slp_s[NE_LP];
__device__ int g_spl_s[NE_PL];
__device__ int g_rp_ll[N_LEGO + 1], g_rp_lp[N_POINT + 1], g_rp_pl[N_LEGO + 1];

// ---------------- helpers ----------------
__device__ __forceinline__ unsigned fkey(float f) {
    unsigned u = __float_as_uint(f);
    return (u & 0x80000000u) ? ~u : (u | 0x80000000u);
}
__device__ __forceinline__ float fdecode(unsigned kk) {
    unsigned u = (kk & 0x80000000u) ? (kk ^ 0x80000000u) : ~kk;
    return __uint_as_float(u);
}
__device__ __forceinline__ uint2 bfsplit2(float v0, float v1) {
    uint32_t h, m;
    asm("cvt.rn.bf16x2.f32 %0, %1, %2;" : "=r"(h) : "f"(v1), "f"(v0));
    float h0 = __uint_as_float(h << 16);
    float h1 = __uint_as_float(h & 0xffff0000u);
    asm("cvt.rn.bf16x2.f32 %0, %1, %2;" : "=r"(m) : "f"(v1 - h1), "f"(v0 - h0));
    return make_uint2(h, m);
}

// ---------------- GEMM (round-7/8 WIN, unchanged) ----------------
#define AHS 20
#define BHS 136
#define AH_OFF 0
#define AM_OFF 2560
#define BH_OFF 5120
#define BM_OFF 7296
#define STAGE_U 9472
#define SMEM_BYTES (2 * STAGE_U * 4)

#define MMA_BF16(accv, a0, a1, a2, a3, b0, b1)                                     \
    asm("mma.sync.aligned.m16n8k16.row.col.f32.bf16.bf16.f32 "                     \
        "{%0,%1,%2,%3}, {%4,%5,%6,%7}, {%8,%9}, {%0,%1,%2,%3};"                    \
        : "+f"(accv[0]), "+f"(accv[1]), "+f"(accv[2]), "+f"(accv[3])               \
        : "r"(a0), "r"(a1), "r"(a2), "r"(a3), "r"(b0), "r"(b1))

#define BF_COMPUTE(sb)                                                             \
    {                                                                              \
        _Pragma("unroll")                                                          \
        for (int kc = 0; kc < 2; kc++) {                                           \
            uint32_t ah[2][4], am[2][4];                                           \
            _Pragma("unroll")                                                      \
            for (int mt = 0; mt < 2; mt++) {                                       \
                int r0 = wm + mt * 16 + g;                                         \
                int o0 = r0 * AHS + kc * 8 + t, o1 = (r0 + 8) * AHS + kc * 8 + t;  \
                ah[mt][0] = (sb)[AH_OFF + o0];     ah[mt][1] = (sb)[AH_OFF + o1];  \
                ah[mt][2] = (sb)[AH_OFF + o0 + 4]; ah[mt][3] = (sb)[AH_OFF + o1 + 4]; \
                am[mt][0] = (sb)[AM_OFF + o0];     am[mt][1] = (sb)[AM_OFF + o1];  \
                am[mt][2] = (sb)[AM_OFF + o0 + 4]; am[mt][3] = (sb)[AM_OFF + o1 + 4]; \
            }                                                                      \
            _Pragma("unroll")                                                      \
            for (int nt = 0; nt < 8; nt++) {                                       \
                int nn = wn + nt * 8 + g;                                          \
                int p0 = (kc * 8 + t) * BHS + nn, p1 = (kc * 8 + t + 4) * BHS + nn;\
                uint32_t b0h = (sb)[BH_OFF + p0], b1h = (sb)[BH_OFF + p1];         \
                uint32_t b0m = (sb)[BM_OFF + p0], b1m = (sb)[BM_OFF + p1];         \
                _Pragma("unroll")                                                  \
                for (int mt = 0; mt < 2; mt++) {                                   \
                    MMA_BF16(acc[mt][nt], am[mt][0], am[mt][1], am[mt][2],         \
                             am[mt][3], b0h, b1h);                                 \
                    MMA_BF16(acc[mt][nt], ah[mt][0], ah[mt][1], ah[mt][2],         \
                             ah[mt][3], b0m, b1m);                                 \
                    MMA_BF16(acc[mt][nt], ah[mt][0], ah[mt][1], ah[mt][2],         \
                             ah[mt][3], b0h, b1h);                                 \
                }                                                                  \
            }                                                                      \
        }                                                                          \
    }

#define STS_A4(sb, row, c4, v4)                                                    \
    {                                                                              \
        int k2c = (c4) >> 1;                                                       \
        uint2 p01 = bfsplit2((v4).x, (v4).y);                                      \
        uint2 p23 = bfsplit2((v4).z, (v4).w);                                      \
        *(uint2*)((sb) + AH_OFF + (row) * AHS + k2c) = make_uint2(p01.x, p23.x);   \
        *(uint2*)((sb) + AM_OFF + (row) * AHS + k2c) = make_uint2(p01.y, p23.y);   \
    }
#define STS_B4(sb, k2, c4, v0, v1)                                                 \
    {                                                                              \
        uint2 q0 = bfsplit2((v0).x, (v1).x);                                       \
        uint2 q1 = bfsplit2((v0).y, (v1).y);                                       \
        uint2 q2 = bfsplit2((v0).z, (v1).z);                                       \
        uint2 q3 = bfsplit2((v0).w, (v1).w);                                       \
        *(uint4*)((sb) + BH_OFF + (k2) * BHS + (c4)) = make_uint4(q0.x, q1.x, q2.x, q3.x); \
        *(uint4*)((sb) + BM_OFF + (k2) * BHS + (c4)) = make_uint4(q0.y, q1.y, q2.y, q3.y); \
    }

__global__ __launch_bounds__(256, 2) void bf3_gemm_kernel(
    const float* __restrict__ A, const float* __restrict__ B,
    const float* __restrict__ bias, float* __restrict__ C,
    int M, int N, int K)
{
    extern __shared__ uint32_t smu[];
    const int tid = threadIdx.x;
    const int warp = tid >> 5, lane = tid & 31;
    const int g = lane >> 2, t = lane & 3;
    const int warp_m = warp & 3, warp_n = warp >> 2;
    const int m_base = blockIdx.y * 128, n_base = blockIdx.x * 128;
    const int wm = warp_m * 32, wn = warp_n * 64;
    const int a_row = tid >> 3, a_c4 = (tid & 7) * 4;
    const int b_k2 = tid >> 5, b_c4 = (tid & 31) * 4;

    float acc[2][8][4];
#pragma unroll
    for (int i = 0; i < 2; i++)
#pragma unroll
        for (int j = 0; j < 8; j++)
#pragma unroll
            for (int c = 0; c < 4; c++) acc[i][j][c] = 0.f;

    float4 av[4], bv0[2], bv1[2];
    const float4 f4z = make_float4(0.f, 0.f, 0.f, 0.f);

#define GEN_LDG(kt)                                                                \
    {                                                                              \
        _Pragma("unroll")                                                          \
        for (int i = 0; i < 4; i++) {                                              \
            int row = a_row + i * 32, gr = m_base + row;                           \
            av[i] = (gr < M) ? *(const float4*)(A + (size_t)gr * K + (kt) + a_c4)  \
                             : f4z;                                                \
        }                                                                          \
        _Pragma("unroll")                                                          \
        for (int i = 0; i < 2; i++) {                                              \
            int k2 = b_k2 + i * 8;                                                 \
            bv0[i] = *(const float4*)(B + (size_t)((kt) + 2 * k2) * N + n_base + b_c4);     \
            bv1[i] = *(const float4*)(B + (size_t)((kt) + 2 * k2 + 1) * N + n_base + b_c4); \
        }                                                                          \
    }
#define GEN_STS(st)                                                                \
    {                                                                              \
        uint32_t* sb = smu + (st) * STAGE_U;                                       \
        _Pragma("unroll")                                                          \
        for (int i = 0; i < 4; i++) STS_A4(sb, a_row + i * 32, a_c4, av[i]);       \
        _Pragma("unroll")                                                          \
        for (int i = 0; i < 2; i++) STS_B4(sb, b_k2 + i * 8, b_c4, bv0[i], bv1[i]);\
    }

    GEN_LDG(0);
    int stage = 0;
    for (int kt = 0; kt < K; kt += 32, stage ^= 1) {
        GEN_STS(stage);
        __syncthreads();
        if (kt + 32 < K) GEN_LDG(kt + 32);
        const uint32_t* sb = smu + stage * STAGE_U;
        BF_COMPUTE(sb);
    }

#pragma unroll
    for (int mt = 0; mt < 2; mt++) {
        int r0 = m_base + wm + mt * 16 + g, r1 = r0 + 8;
#pragma unroll
        for (int nt = 0; nt < 8; nt++) {
            int c = n_base + wn + nt * 8 + 2 * t;
            float b0 = 0.f, b1 = 0.f;
            if (bias) { b0 = bias[c]; b1 = bias[c + 1]; }
            if (r0 < M) *(float2*)(C + (size_t)r0 * N + c) =
                make_float2(acc[mt][nt][0] + b0, acc[mt][nt][1] + b1);
            if (r1 < M) *(float2*)(C + (size_t)r1 * N + c) =
                make_float2(acc[mt][nt][2] + b0, acc[mt][nt][3] + b1);
        }
    }
}

// ---------------- fused EdgeConv MLP2 + segment-max (round-8 WIN, unchanged) ----------------
__global__ __launch_bounds__(256, 2) void edge_bf3_kernel(
    const float* __restrict__ PQ, const float* __restrict__ b1,
    const float* __restrict__ W2,
    const int* __restrict__ src, const int* __restrict__ dst,
    unsigned* __restrict__ emax, int E)
{
    extern __shared__ uint32_t smu[];
    __shared__ int se[128], de[128];
    const int tid = threadIdx.x;
    const int warp = tid >> 5, lane = tid & 31;
    const int g = lane >> 2, t = lane & 3;
    const int warp_m = warp & 3, warp_n = warp >> 2;
    const int e_base = blockIdx.y * 128;
    const int wm = warp_m * 32, wn = warp_n * 64;
    const int a_row = tid >> 3, a_c4 = (tid & 7) * 4;
    const int b_k2 = tid >> 5, b_c4 = (tid & 31) * 4;

    if (tid < 128) {
        int e = e_base + tid;
        bool ok = (e < E);
        se[tid] = ok ? src[e] : 0;
        de[tid] = ok ? dst[e] : 0;
    }
    __syncthreads();

    float acc[2][8][4];
#pragma unroll
    for (int i = 0; i < 2; i++)
#pragma unroll
        for (int j = 0; j < 8; j++)
#pragma unroll
            for (int c = 0; c < 4; c++) acc[i][j][c] = 0.f;

    float4 bv0[2], bv1[2];

#define EB_LDG(kt)                                                                 \
    {                                                                              \
        _Pragma("unroll")                                                          \
        for (int i = 0; i < 2; i++) {                                              \
            int k2 = b_k2 + i * 8;                                                 \
            bv0[i] = *(const float4*)(W2 + (size_t)((kt) + 2 * k2) * 128 + b_c4);     \
            bv1[i] = *(const float4*)(W2 + (size_t)((kt) + 2 * k2 + 1) * 128 + b_c4); \
        }                                                                          \
    }
#define EB_B_STS(st)                                                               \
    {                                                                              \
        uint32_t* sb = smu + (st) * STAGE_U;                                       \
        _Pragma("unroll")                                                          \
        for (int i = 0; i < 2; i++) STS_B4(sb, b_k2 + i * 8, b_c4, bv0[i], bv1[i]);\
    }
#define EB_A_STS(kt, st)                                                           \
    {                                                                              \
        uint32_t* sb = smu + (st) * STAGE_U;                                       \
        float4 bb = *(const float4*)(b1 + (kt) + a_c4);                            \
        _Pragma("unroll")                                                          \
        for (int i = 0; i < 4; i++) {                                              \
            int row = a_row + i * 32;                                              \
            size_t dof = (size_t)de[row] * 1024, sof = (size_t)se[row] * 1024 + 512; \
            float4 rv = *(const float4*)(PQ + dof + (kt) + a_c4);                  \
            float4 qv = *(const float4*)(PQ + sof + (kt) + a_c4);                  \
            float4 h;                                                              \
            h.x = fmaxf(rv.x + qv.x + bb.x, 0.f);                                  \
            h.y = fmaxf(rv.y + qv.y + bb.y, 0.f);                                  \
            h.z = fmaxf(rv.z + qv.z + bb.z, 0.f);                                  \
            h.w = fmaxf(rv.w + qv.w + bb.w, 0.f);                                  \
            STS_A4(sb, row, a_c4, h);                                              \
        }                                                                          \
    }

    EB_A_STS(0, 0);
    EB_LDG(0);
    int stage = 0;
    for (int kt = 0; kt < 512; kt += 32, stage ^= 1) {
        EB_B_STS(stage);
        __syncthreads();
        if (kt + 32 < 512) EB_LDG(kt + 32);
        const uint32_t* sb = smu + stage * STAGE_U;
        BF_COMPUTE(sb);
        if (kt + 32 < 512) EB_A_STS(kt + 32, stage ^ 1);
    }

#pragma unroll
    for (int mt = 0; mt < 2; mt++) {
        int r0 = wm + mt * 16 + g, r1 = r0 + 8;
        int e0 = e_base + r0, e1 = e_base + r1;
        int d0 = de[r0], d1 = de[r1];
#pragma unroll
        for (int nt = 0; nt < 8; nt++) {
            int c = wn + nt * 8 + 2 * t;
            if (e0 < E) {
                atomicMax(emax + (size_t)d0 * DIMF + c,     fkey(acc[mt][nt][0]));
                atomicMax(emax + (size_t)d0 * DIMF + c + 1, fkey(acc[mt][nt][1]));
            }
            if (e1 < E) {
                atomicMax(emax + (size_t)d1 * DIMF + c,     fkey(acc[mt][nt][2]));
                atomicMax(emax + (size_t)d1 * DIMF + c + 1, fkey(acc[mt][nt][3]));
            }
        }
    }
}

// ---------------- CSR-fused attention kernels (round-14 WIN, unchanged) ----------------
__global__ void trans_fused_kernel(
    const float* __restrict__ qkvs, const int* __restrict__ rowptr,
    const int* __restrict__ srcs, float* __restrict__ escore,
    float* __restrict__ out, int n, float scale)
{
    int idx = blockIdx.x * blockDim.x + threadIdx.x;
    int d = idx >> 5, lane = idx & 31;
    if (d >= n) return;
    int beg = rowptr[d], end = rowptr[d + 1];
    if (beg == end) return;
    float4 q = *(const float4*)(qkvs + (size_t)d * 512 + lane * 4);
    float m = -INFINITY;
    for (int e = beg; e < end; e++) {
        int s0 = srcs[e];
        float4 kv = *(const float4*)(qkvs + (size_t)s0 * 512 + 128 + lane * 4);
        float s = q.x * kv.x + q.y * kv.y + q.z * kv.z + q.w * kv.w;
#pragma unroll
        for (int o = 16; o; o >>= 1) s += __shfl_xor_sync(0xffffffffu, s, o);
        s *= scale;
        if (lane == 0) escore[e] = s;
        m = fmaxf(m, s);
    }
    __syncwarp();
    float4 acc = make_float4(0.f, 0.f, 0.f, 0.f);
    float dsum = 0.f;
    for (int e = beg; e < end; e++) {
        float ex = expf(escore[e] - m);
        dsum += ex;
        int s0 = srcs[e];
        float4 vv = *(const float4*)(qkvs + (size_t)s0 * 512 + 256 + lane * 4);
        acc.x += ex * vv.x; acc.y += ex * vv.y;
        acc.z += ex * vv.z; acc.w += ex * vv.w;
    }
    float inv = 1.f / (dsum + 1e-16f);
    float* op = out + (size_t)d * DIMF + lane * 4;
    float4 o = *(float4*)op;
    o.x += acc.x * inv; o.y += acc.y * inv;
    o.z += acc.z * inv; o.w += acc.w * inv;
    *(float4*)op = o;
}

__global__ void gat_fused_kernel(
    const float* __restrict__ ss, const float* __restrict__ sd,
    const float* __restrict__ hs, const int* __restrict__ rowptr,
    const int* __restrict__ srcs, float* __restrict__ escore,
    const float* __restrict__ gb, float* __restrict__ out, int n)
{
    int idx = blockIdx.x * blockDim.x + threadIdx.x;
    int d = idx >> 5, lane = idx & 31;
    if (d >= n) return;
    float* op = out + (size_t)d * DIMF + lane * 4;
    float4 o = *(float4*)op;
    float4 bv = *(const float4*)(gb + lane * 4);
    o.x += bv.x; o.y += bv.y; o.z += bv.z; o.w += bv.w;
    int beg = rowptr[d], end = rowptr[d + 1];
    if (beg < end) {
        float sdd = sd[d];
        float m = -INFINITY;
        for (int e = beg + lane; e < end; e += 32) {
            float s = ss[srcs[e]] + sdd;
            s = (s > 0.f) ? s : 0.2f * s;
            escore[e] = s;
            m = fmaxf(m, s);
        }
#pragma unroll
        for (int oo = 16; oo; oo >>= 1) m = fmaxf(m, __shfl_xor_sync(0xffffffffu, m, oo));
        __syncwarp();
        float4 acc = make_float4(0.f, 0.f, 0.f, 0.f);
        float dsum = 0.f;
        for (int e = beg; e < end; e++) {
            float ex = expf(escore[e] - m);
            dsum += ex;
            int s0 = srcs[e];
            float4 hv = *(const float4*)(hs + (size_t)s0 * DIMF + lane * 4);
            acc.x += ex * hv.x; acc.y += ex * hv.y;
            acc.z += ex * hv.z; acc.w += ex * hv.w;
        }
        float inv = 1.f / (dsum + 1e-16f);
        o.x += acc.x * inv; o.y += acc.y * inv;
        o.z += acc.z * inv; o.w += acc.w * inv;
    }
    *(float4*)op = o;
}

// ---------------- one-time weight prep ----------------
__global__ void concat_trans_kernel(const float* Wq, const float* Wk, const float* Wv,
                                    const float* Ws, const float* bq, const float* bk,
                                    const float* bv, const float* bs,
                                    float* Wcat, float* bcat)
{
    int i = blockIdx.x * blockDim.x + threadIdx.x;
    if (i >= 4 * 128 * 512) return;
    int inst = i >> 16, r = (i >> 9) & 127, j = i & 511;
    int sel = j >> 7, jj = j & 127;
    const float* W = sel == 0 ? Wq : sel == 1 ? Wk : sel == 2 ? Wv : Ws;
    Wcat[i] = W[((size_t)inst * 128 + r) * 128 + jj];
    if (r == 0) {
        const float* bb = sel == 0 ? bq : sel == 1 ? bk : sel == 2 ? bv : bs;
        bcat[inst * 512 + j] = bb[inst * 128 + jj];
    }
}
__global__ void concat_edge_kernel(const float* W1, float* Wcat)
{
    int i = blockIdx.x * blockDim.x + threadIdx.x;
    if (i >= 4 * 128 * 1024) return;
    int inst = i >> 17, r = (i >> 10) & 127, j = i & 1023;
    const float* Wi = W1 + (size_t)inst * 256 * 512;
    if (j < 512) Wcat[i] = Wi[(size_t)r * 512 + j] - Wi[(size_t)(128 + r) * 512 + j];
    else         Wcat[i] = Wi[(size_t)(128 + r) * 512 + (j - 512)];
}
__global__ void wadall_kernel(const float* __restrict__ gW, const float* __restrict__ gAd,
                              float* __restrict__ wad)
{
    int b = blockIdx.x, j = threadIdx.x;
    float s = 0.f;
    for (int kk = 0; kk < 128; kk++)
        s += gW[((size_t)b * 128 + j) * 128 + kk] * gAd[b * 128 + kk];
    wad[b * 128 + j] = s;
}

// ---------------- batched counting sort (all 4 relations in one pipeline) ----------------
__global__ void fill_i32_kernel(int* p, int val, int n) {
    int i = blockIdx.x * blockDim.x + threadIdx.x;
    if (i < n) p[i] = val;
}
__global__ void count4_kernel(const int* __restrict__ lld, const int* __restrict__ ppd,
                              const int* __restrict__ lpd, const int* __restrict__ pld,
                              int* __restrict__ hist)
{
    int e = blockIdx.x * blockDim.x + threadIdx.x;
    if (e >= E_TOT) return;
    int d;
    if (e < F_PP)      d = O_LL + lld[e];
    else if (e < F_LP) d = O_PP + ppd[e - F_PP];
    else if (e < F_PL) d = O_LP + lpd[e - F_LP];
    else               d = O_PL + pld[e - F_PL];
    atomicAdd(hist + d, 1);
}
__global__ void scan1_kernel(const int* __restrict__ hist, int* __restrict__ off,
                             int* __restrict__ bsum, int n) {
    __shared__ int sh[SCAN_B];
    int tid = threadIdx.x, i = blockIdx.x * SCAN_B + tid;
    int v = (i < n) ? hist[i] : 0;
    sh[tid] = v; __syncthreads();
    for (int d = 1; d < SCAN_B; d <<= 1) {
        int t2 = (tid >= d) ? sh[tid - d] : 0;
        __syncthreads(); sh[tid] += t2; __syncthreads();
    }
    if (i < n) off[i] = sh[tid] - v;
    if (tid == SCAN_B - 1) bsum[blockIdx.x] = sh[tid];
}
__global__ void scan2_kernel(int* __restrict__ bsum, int nb) {
    __shared__ int sh[SCAN_B];
    int tid = threadIdx.x;
    int v = (tid < nb) ? bsum[tid] : 0;
    sh[tid] = v; __syncthreads();
    for (int d = 1; d < SCAN_B; d <<= 1) {
        int t2 = (tid >= d) ? sh[tid - d] : 0;
        __syncthreads(); sh[tid] += t2; __syncthreads();
    }
    if (tid < nb) bsum[tid] = sh[tid] - v;
}
// global offsets + per-relation rowptrs + sentinels
__global__ void scan3_kernel(const int* __restrict__ off, const int* __restrict__ bsum,
                             int* __restrict__ work,
                             int* __restrict__ rp_ll, int* __restrict__ rp_lp,
                             int* __restrict__ rp_pl)
{
    int i = blockIdx.x * blockDim.x + threadIdx.x;
    if (i < NT_NODES) {
        int v = off[i] + bsum[i / SCAN_B];
        work[i] = v;
        if (i < O_PP)                       rp_ll[i] = v - F_LL;
        else if (i >= O_LP && i < O_PL)     rp_lp[i - O_LP] = v - F_LP;
        else if (i >= O_PL)                 rp_pl[i - O_PL] = v - F_PL;
    }
    if (i == 0) {
        rp_ll[N_LEGO]  = NE_LL;
        rp_lp[N_POINT] = NE_LP;
        rp_pl[N_LEGO]  = NE_PL;
    }
}
__global__ void scatter4_kernel(
    const int* __restrict__ lls, const int* __restrict__ lld,
    const int* __restrict__ pps, const int* __restrict__ ppd,
    const int* __restrict__ lps, const int* __restrict__ lpd,
    const int* __restrict__ pls, const int* __restrict__ pld,
    int* __restrict__ work,
    int* __restrict__ oll, int* __restrict__ opp_s, int* __restrict__ opp_d,
    int* __restrict__ olp, int* __restrict__ opl)
{
    int e = blockIdx.x * blockDim.x + threadIdx.x;
    if (e >= E_TOT) return;
    if (e < F_PP) {
        int d = lld[e];
        int pos = atomicAdd(work + O_LL + d, 1);
        oll[pos - F_LL] = lls[e];
    } else if (e < F_LP) {
        int el = e - F_PP;
        int d = ppd[el];
        int pos = atomicAdd(work + O_PP + d, 1) - F_PP;
        opp_s[pos] = pps[el];
        opp_d[pos] = d;
    } else if (e < F_PL) {
        int el = e - F_LP;
        int d = lpd[el];
        int pos = atomicAdd(work + O_LP + d, 1);
        olp[pos - F_LP] = lps[el];
    } else {
        int el = e - F_PL;
        int d = pld[el];
        int pos = atomicAdd(work + O_PL + d, 1);
        opl[pos - F_PL] = pls[el];
    }
}

// ---------------- small glue kernels ----------------
__global__ void fill_u32_kernel(unsigned* p, unsigned val, int n) {
    int i = blockIdx.x * blockDim.x + threadIdx.x;
    if (i < n) p[i] = val;
}
__global__ void copy_skip_kernel(const float* __restrict__ qkvs, float* __restrict__ out, int n) {
    int i = blockIdx.x * blockDim.x + threadIdx.x;
    if (i >= n * 32) return;
    int row = i >> 5, f = (i & 31) * 4;
    *(float4*)(out + (size_t)row * DIMF + f) =
        *(const float4*)(qkvs + (size_t)row * 512 + 384 + f);
}
__global__ void node_dot_kernel(const float* __restrict__ h, const float* __restrict__ avec,
                                float* __restrict__ out, int n)
{
    int idx = blockIdx.x * blockDim.x + threadIdx.x;
    int i = idx >> 5, lane = idx & 31;
    if (i >= n) return;
    float4 hv = *(const float4*)(h + (size_t)i * DIMF + lane * 4);
    float4 av = *(const float4*)(avec + lane * 4);
    float s = hv.x * av.x + hv.y * av.y + hv.z * av.z + hv.w * av.w;
#pragma unroll
    for (int o = 16; o; o >>= 1) s += __shfl_xor_sync(0xffffffffu, s, o);
    if (lane == 0) out[i] = s;
}
// finalize + reset emax for the next edge pass (saves one fill kernel per call)
__global__ void finalize_max_b2_kernel(unsigned* __restrict__ emax,
                                       const float* __restrict__ b2,
                                       float* __restrict__ out, int total) {
    int i = blockIdx.x * blockDim.x + threadIdx.x;
    if (i >= total) return;
    float v = fdecode(emax[i]);
    out[i] = isfinite(v) ? v + b2[i & (DIMF - 1)] : 0.f;
    emax[i] = NEG_INF_KEY;
}

// ---------------- host orchestration ----------------
static inline int div_up(int a, int b) { return (a + b - 1) / b; }

struct Scratch {
    float *xl, *xp, *la, *pa, *hs, *ss, *sd, *escore, *PQ;
    float *WcatT, *bcatT, *WcatE, *wadall;
    unsigned *emax;
    int *hist4, *work4, *bsum;
    int *sll_s, *spp_s, *spp_d, *slp_s, *spl_s;
    int *rp_ll, *rp_lp, *rp_pl;
};

static void sgemm(const float* A, const float* B, const float* bias, float* C,
                  int M, int N, int K) {
    dim3 grid(N / 128, div_up(M, 128));
    bf3_gemm_kernel<<<grid, 256, SMEM_BYTES>>>(A, B, bias, C, M, N, K);
}

static void run_trans(const Scratch& S, const float* x, int n, int inst,
                      const int* rowptr, const int* srcs, float* out)
{
    sgemm(x, S.WcatT + (size_t)inst * 128 * 512, S.bcatT + inst * 512, S.PQ, n, 512, DIMF);
    copy_skip_kernel<<<div_up(n * 32, 256), 256>>>(S.PQ, out, n);
    float scale = 1.f / sqrtf((float)DIMF);
    trans_fused_kernel<<<div_up(n * 32, 256), 256>>>(S.PQ, rowptr, srcs, S.escore,
                                                     out, n, scale);
}

static void run_gat(const Scratch& S, const float* xs, int ns, const float* xd, int nd,
                    const int* rowptr, const int* srcs, int inst,
                    const float* W, const float* a_src, const float* gb, float* out)
{
    sgemm(xs, W, nullptr, S.hs, ns, DIMF, DIMF);
    node_dot_kernel<<<div_up(ns * 32, 256), 256>>>(S.hs, a_src, S.ss, ns);
    node_dot_kernel<<<div_up(nd * 32, 256), 256>>>(xd, S.wadall + inst * 128, S.sd, nd);
    gat_fused_kernel<<<div_up(nd * 32, 256), 256>>>(S.ss, S.sd, S.hs, rowptr, srcs,
                                                    S.escore, gb, out, nd);
}

static void run_edge(const Scratch& S, const float* x, int n, int inst,
                     const int* src, const int* dst, int E,
                     const float* b1, const float* W2, const float* b2, float* out)
{
    sgemm(x, S.WcatE + (size_t)inst * 128 * 1024, nullptr, S.PQ, n, 1024, DIMF);
    dim3 grid(1, div_up(E, 128));
    edge_bf3_kernel<<<grid, 256, SMEM_BYTES>>>(S.PQ, b1, W2, src, dst, S.emax, E);
    finalize_max_b2_kernel<<<div_up(n * DIMF, 256), 256>>>(S.emax, b2, out, n * DIMF);
}

extern "C" void kernel_launch(void* const* d_in, const int* in_sizes, int n_in,
                              void* d_out, int out_size)
{
    const float* x_lego  = (const float*)d_in[0];
    const float* x_point = (const float*)d_in[1];
    const float* tWq = (const float*)d_in[2];
    const float* tbq = (const float*)d_in[3];
    const float* tWk = (const float*)d_in[4];
    const float* tbk = (const float*)d_in[5];
    const float* tWv = (const float*)d_in[6];
    const float* tbv = (const float*)d_in[7];
    const float* tWs = (const float*)d_in[8];
    const float* tbs = (const float*)d_in[9];
    const float* eW1 = (const float*)d_in[10];
    const float* eb1 = (const float*)d_in[11];
    const float* eW2 = (const float*)d_in[12];
    const float* eb2 = (const float*)d_in[13];
    const float* gW  = (const float*)d_in[14];
    const float* gAs = (const float*)d_in[15];
    const float* gAd = (const float*)d_in[16];
    const float* gb  = (const float*)d_in[17];
    const int* ll_src = (const int*)d_in[18];
    const int* ll_dst = (const int*)d_in[19];
    const int* pp_src = (const int*)d_in[20];
    const int* pp_dst = (const int*)d_in[21];
    const int* lp_src = (const int*)d_in[22];
    const int* lp_dst = (const int*)d_in[23];
    const int* pl_src = (const int*)d_in[24];
    const int* pl_dst = (const int*)d_in[25];

    cudaFuncSetAttribute(bf3_gemm_kernel, cudaFuncAttributeMaxDynamicSharedMemorySize,
                         SMEM_BYTES);
    cudaFuncSetAttribute(edge_bf3_kernel, cudaFuncAttributeMaxDynamicSharedMemorySize,
                         SMEM_BYTES);

    Scratch S;
    cudaGetSymbolAddress((void**)&S.xl, g_xl);
    cudaGetSymbolAddress((void**)&S.xp, g_xp);
    cudaGetSymbolAddress((void**)&S.la, g_la);
    cudaGetSymbolAddress((void**)&S.pa, g_pa);
    cudaGetSymbolAddress((void**)&S.hs, g_hs);
    cudaGetSymbolAddress((void**)&S.ss, g_ss);
    cudaGetSymbolAddress((void**)&S.sd, g_sd);
    cudaGetSymbolAddress((void**)&S.escore, g_escore);
    cudaGetSymbolAddress((void**)&S.PQ, g_PQ);
    cudaGetSymbolAddress((void**)&S.emax, g_emax);
    cudaGetSymbolAddress((void**)&S.WcatT, g_WcatT);
    cudaGetSymbolAddress((void**)&S.bcatT, g_bcatT);
    cudaGetSymbolAddress((void**)&S.WcatE, g_WcatE);
    cudaGetSymbolAddress((void**)&S.wadall, g_wadall);
    cudaGetSymbolAddress((void**)&S.hist4, g_hist4);
    cudaGetSymbolAddress((void**)&S.work4, g_work4);
    cudaGetSymbolAddress((void**)&S.bsum, g_bsum);
    cudaGetSymbolAddress((void**)&S.sll_s, g_sll_s);
    cudaGetSymbolAddress((void**)&S.spp_s, g_spp_s);
    cudaGetSymbolAddress((void**)&S.spp_d, g_spp_d);
    cudaGetSymbolAddress((void**)&S.slp_s, g_slp_s);
    cudaGetSymbolAddress((void**)&S.spl_s, g_spl_s);
    cudaGetSymbolAddress((void**)&S.rp_ll, g_rp_ll);
    cudaGetSymbolAddress((void**)&S.rp_lp, g_rp_lp);
    cudaGetSymbolAddress((void**)&S.rp_pl, g_rp_pl);

    cudaMemcpyAsync(S.xl, x_lego,  (size_t)N_LEGO * DIMF * sizeof(float),  cudaMemcpyDeviceToDevice);
    cudaMemcpyAsync(S.xp, x_point, (size_t)N_POINT * DIMF * sizeof(float), cudaMemcpyDeviceToDevice);

    // weight prep + emax init (finalize resets it after each use)
    concat_trans_kernel<<<div_up(4 * 128 * 512, 256), 256>>>(tWq, tWk, tWv, tWs,
                                                             tbq, tbk, tbv, tbs,
                                                             S.WcatT, S.bcatT);
    concat_edge_kernel<<<div_up(4 * 128 * 1024, 256), 256>>>(eW1, S.WcatE);
    wadall_kernel<<<4, 128>>>(gW, gAd, S.wadall);
    fill_u32_kernel<<<div_up(N_POINT * DIMF, 256), 256>>>(S.emax, NEG_INF_KEY, N_POINT * DIMF);

    // batched sort of all 4 edge lists
    fill_i32_kernel<<<div_up(NT_NODES, 256), 256>>>(S.hist4, 0, NT_NODES);
    count4_kernel<<<div_up(E_TOT, 256), 256>>>(ll_dst, pp_dst, lp_dst, pl_dst, S.hist4);
    int nb = div_up(NT_NODES, SCAN_B);
    scan1_kernel<<<nb, SCAN_B>>>(S.hist4, S.work4, S.bsum, NT_NODES);
    scan2_kernel<<<1, SCAN_B>>>(S.bsum, nb);
    scan3_kernel<<<div_up(NT_NODES, 256), 256>>>(S.work4, S.bsum, S.hist4,
                                                 S.rp_ll, S.rp_lp, S.rp_pl);
    scatter4_kernel<<<div_up(E_TOT, 256), 256>>>(ll_src, ll_dst, pp_src, pp_dst,
                                                 lp_src, lp_dst, pl_src, pl_dst,
                                                 S.hist4, S.sll_s, S.spp_s, S.spp_d,
                                                 S.slp_s, S.spl_s);

    for (int layer = 0; layer < 2; layer++) {
        int iA = 2 * layer, iB = 2 * layer + 1;
        int i_lp = 2 * layer, i_pl = 2 * layer + 1;

        run_trans(S, S.xl, N_LEGO, iA, S.rp_ll, S.sll_s, S.la);
        run_gat(S, S.xp, N_POINT, S.xl, N_LEGO, S.rp_pl, S.spl_s, i_pl,
                gW + i_pl * DIMF * DIMF, gAs + i_pl * DIMF, gb + i_pl * DIMF, S.la);

        run_edge(S, S.xp, N_POINT, iA, S.spp_s, S.spp_d, NE_PP,
                 eb1 + iA * 512, eW2 + (size_t)iA * 512 * DIMF, eb2 + iA * DIMF, S.pa);
        run_gat(S, S.xl, N_LEGO, S.xp, N_POINT, S.rp_lp, S.slp_s, i_lp,
                gW + i_lp * DIMF * DIMF, gAs + i_lp * DIMF, gb + i_lp * DIMF, S.pa);

        run_trans(S, S.la, N_LEGO, iB, S.rp_ll, S.sll_s, S.xl);
        run_edge(S, S.pa, N_POINT, iB, S.spp_s, S.spp_d, NE_PP,
                 eb1 + iB * 512, eW2 + (size_t)iB * 512 * DIMF, eb2 + iB * DIMF, S.xp);
    }

    float* out = (float*)d_out;
    cudaMemcpyAsync(out, S.xl, (size_t)N_LEGO * DIMF * sizeof(float), cudaMemcpyDeviceToDevice);
    cudaMemcpyAsync(out + (size_t)N_LEGO * DIMF, S.xp, (size_t)N_POINT * DIMF * sizeof(float),
                    cudaMemcpyDeviceToDevice);
}

// round 16
// speedup vs baseline: 1.1485x; 1.0792x over previous
#include <cuda_runtime.h>
#include <math.h>
#include <stdint.h>

#define DIMF 128
#define N_LEGO 50000
#define N_POINT 100000
#define NE_LL 500000
#define NE_PP 400000
#define NE_LP 500000
#define NE_PL 500000
#define NEG_INF_KEY 0x007FFFFFu
#define SCAN_B 1024
#define O_LL 0
#define O_PP N_LEGO
#define O_LP (N_LEGO + N_POINT)
#define O_PL (N_LEGO + 2 * N_POINT)
#define NT_NODES (2 * N_LEGO + 2 * N_POINT)
#define F_LL 0
#define F_PP NE_LL
#define F_LP (NE_LL + NE_PP)
#define F_PL (NE_LL + NE_PP + NE_LP)
#define E_TOT (NE_LL + NE_PP + NE_LP + NE_PL)

// ---------------- scratch ----------------
__device__ float    g_xl[N_LEGO * DIMF];
__device__ float    g_xp[N_POINT * DIMF];
__device__ float    g_la[N_LEGO * DIMF];
__device__ float    g_pa[N_POINT * DIMF];
__device__ float    g_hs[N_POINT * DIMF];
__device__ float    g_ss[N_POINT];
__device__ float    g_sd[N_POINT];
__device__ float    g_escore[NE_LL];
__device__ float    g_PQ[(size_t)N_POINT * 1024];
__device__ unsigned g_emax[N_POINT * DIMF];
__device__ float    g_WcatT[4 * 128 * 512];
__device__ float    g_bcatT[4 * 512];
__device__ float    g_WcatE[4 * 128 * 1024];
__device__ float    g_wadall[4 * 128];
__device__ int g_hist4[NT_NODES], g_work4[NT_NODES], g_bsum[SCAN_B];
__device__ int g_sll_s[NE_LL];
__device__ int g_spp_s[NE_PP], g_spp_d[NE_PP];
__device__ int g_slp_s[NE_LP];
__device__ int g_spl_s[NE_PL];
__device__ int g_rp_ll[N_LEGO + 1], g_rp_lp[N_POINT + 1], g_rp_pl[N_LEGO + 1];

// ---------------- helpers ----------------
__device__ __forceinline__ unsigned fkey(float f) {
    unsigned u = __float_as_uint(f);
    return (u & 0x80000000u) ? ~u : (u | 0x80000000u);
}
__device__ __forceinline__ float fdecode(unsigned kk) {
    unsigned u = (kk & 0x80000000u) ? (kk ^ 0x80000000u) : ~kk;
    return __uint_as_float(u);
}
__device__ __forceinline__ uint2 bfsplit2(float v0, float v1) {
    uint32_t h, m;
    asm("cvt.rn.bf16x2.f32 %0, %1, %2;" : "=r"(h) : "f"(v1), "f"(v0));
    float h0 = __uint_as_float(h << 16);
    float h1 = __uint_as_float(h & 0xffff0000u);
    asm("cvt.rn.bf16x2.f32 %0, %1, %2;" : "=r"(m) : "f"(v1 - h1), "f"(v0 - h0));
    return make_uint2(h, m);
}
__device__ __forceinline__ void pref_l2(const void* p) {
    asm volatile("prefetch.global.L2 [%0];" :: "l"(p));
}

// ---------------- GEMM (round-7/8 WIN, unchanged) ----------------
#define AHS 20
#define BHS 136
#define AH_OFF 0
#define AM_OFF 2560
#define BH_OFF 5120
#define BM_OFF 7296
#define STAGE_U 9472
#define SMEM_BYTES (2 * STAGE_U * 4)

#define MMA_BF16(accv, a0, a1, a2, a3, b0, b1)                                     \
    asm("mma.sync.aligned.m16n8k16.row.col.f32.bf16.bf16.f32 "                     \
        "{%0,%1,%2,%3}, {%4,%5,%6,%7}, {%8,%9}, {%0,%1,%2,%3};"                    \
        : "+f"(accv[0]), "+f"(accv[1]), "+f"(accv[2]), "+f"(accv[3])               \
        : "r"(a0), "r"(a1), "r"(a2), "r"(a3), "r"(b0), "r"(b1))

#define BF_COMPUTE(sb)                                                             \
    {                                                                              \
        _Pragma("unroll")                                                          \
        for (int kc = 0; kc < 2; kc++) {                                           \
            uint32_t ah[2][4], am[2][4];                                           \
            _Pragma("unroll")                                                      \
            for (int mt = 0; mt < 2; mt++) {                                       \
                int r0 = wm + mt * 16 + g;                                         \
                int o0 = r0 * AHS + kc * 8 + t, o1 = (r0 + 8) * AHS + kc * 8 + t;  \
                ah[mt][0] = (sb)[AH_OFF + o0];     ah[mt][1] = (sb)[AH_OFF + o1];  \
                ah[mt][2] = (sb)[AH_OFF + o0 + 4]; ah[mt][3] = (sb)[AH_OFF + o1 + 4]; \
                am[mt][0] = (sb)[AM_OFF + o0];     am[mt][1] = (sb)[AM_OFF + o1];  \
                am[mt][2] = (sb)[AM_OFF + o0 + 4]; am[mt][3] = (sb)[AM_OFF + o1 + 4]; \
            }                                                                      \
            _Pragma("unroll")                                                      \
            for (int nt = 0; nt < 8; nt++) {                                       \
                int nn = wn + nt * 8 + g;                                          \
                int p0 = (kc * 8 + t) * BHS + nn, p1 = (kc * 8 + t + 4) * BHS + nn;\
                uint32_t b0h = (sb)[BH_OFF + p0], b1h = (sb)[BH_OFF + p1];         \
                uint32_t b0m = (sb)[BM_OFF + p0], b1m = (sb)[BM_OFF + p1];         \
                _Pragma("unroll")                                                  \
                for (int mt = 0; mt < 2; mt++) {                                   \
                    MMA_BF16(acc[mt][nt], am[mt][0], am[mt][1], am[mt][2],         \
                             am[mt][3], b0h, b1h);                                 \
                    MMA_BF16(acc[mt][nt], ah[mt][0], ah[mt][1], ah[mt][2],         \
                             ah[mt][3], b0m, b1m);                                 \
                    MMA_BF16(acc[mt][nt], ah[mt][0], ah[mt][1], ah[mt][2],         \
                             ah[mt][3], b0h, b1h);                                 \
                }                                                                  \
            }                                                                      \
        }                                                                          \
    }

#define STS_A4(sb, row, c4, v4)                                                    \
    {                                                                              \
        int k2c = (c4) >> 1;                                                       \
        uint2 p01 = bfsplit2((v4).x, (v4).y);                                      \
        uint2 p23 = bfsplit2((v4).z, (v4).w);                                      \
        *(uint2*)((sb) + AH_OFF + (row) * AHS + k2c) = make_uint2(p01.x, p23.x);   \
        *(uint2*)((sb) + AM_OFF + (row) * AHS + k2c) = make_uint2(p01.y, p23.y);   \
    }
#define STS_B4(sb, k2, c4, v0, v1)                                                 \
    {                                                                              \
        uint2 q0 = bfsplit2((v0).x, (v1).x);                                       \
        uint2 q1 = bfsplit2((v0).y, (v1).y);                                       \
        uint2 q2 = bfsplit2((v0).z, (v1).z);                                       \
        uint2 q3 = bfsplit2((v0).w, (v1).w);                                       \
        *(uint4*)((sb) + BH_OFF + (k2) * BHS + (c4)) = make_uint4(q0.x, q1.x, q2.x, q3.x); \
        *(uint4*)((sb) + BM_OFF + (k2) * BHS + (c4)) = make_uint4(q0.y, q1.y, q2.y, q3.y); \
    }

__global__ __launch_bounds__(256, 2) void bf3_gemm_kernel(
    const float* __restrict__ A, const float* __restrict__ B,
    const float* __restrict__ bias, float* __restrict__ C,
    int M, int N, int K)
{
    extern __shared__ uint32_t smu[];
    const int tid = threadIdx.x;
    const int warp = tid >> 5, lane = tid & 31;
    const int g = lane >> 2, t = lane & 3;
    const int warp_m = warp & 3, warp_n = warp >> 2;
    const int m_base = blockIdx.y * 128, n_base = blockIdx.x * 128;
    const int wm = warp_m * 32, wn = warp_n * 64;
    const int a_row = tid >> 3, a_c4 = (tid & 7) * 4;
    const int b_k2 = tid >> 5, b_c4 = (tid & 31) * 4;

    float acc[2][8][4];
#pragma unroll
    for (int i = 0; i < 2; i++)
#pragma unroll
        for (int j = 0; j < 8; j++)
#pragma unroll
            for (int c = 0; c < 4; c++) acc[i][j][c] = 0.f;

    float4 av[4], bv0[2], bv1[2];
    const float4 f4z = make_float4(0.f, 0.f, 0.f, 0.f);

#define GEN_LDG(kt)                                                                \
    {                                                                              \
        _Pragma("unroll")                                                          \
        for (int i = 0; i < 4; i++) {                                              \
            int row = a_row + i * 32, gr = m_base + row;                           \
            av[i] = (gr < M) ? *(const float4*)(A + (size_t)gr * K + (kt) + a_c4)  \
                             : f4z;                                                \
        }                                                                          \
        _Pragma("unroll")                                                          \
        for (int i = 0; i < 2; i++) {                                              \
            int k2 = b_k2 + i * 8;                                                 \
            bv0[i] = *(const float4*)(B + (size_t)((kt) + 2 * k2) * N + n_base + b_c4);     \
            bv1[i] = *(const float4*)(B + (size_t)((kt) + 2 * k2 + 1) * N + n_base + b_c4); \
        }                                                                          \
    }
#define GEN_STS(st)                                                                \
    {                                                                              \
        uint32_t* sb = smu + (st) * STAGE_U;                                       \
        _Pragma("unroll")                                                          \
        for (int i = 0; i < 4; i++) STS_A4(sb, a_row + i * 32, a_c4, av[i]);       \
        _Pragma("unroll")                                                          \
        for (int i = 0; i < 2; i++) STS_B4(sb, b_k2 + i * 8, b_c4, bv0[i], bv1[i]);\
    }

    GEN_LDG(0);
    int stage = 0;
    for (int kt = 0; kt < K; kt += 32, stage ^= 1) {
        GEN_STS(stage);
        __syncthreads();
        if (kt + 32 < K) GEN_LDG(kt + 32);
        const uint32_t* sb = smu + stage * STAGE_U;
        BF_COMPUTE(sb);
    }

#pragma unroll
    for (int mt = 0; mt < 2; mt++) {
        int r0 = m_base + wm + mt * 16 + g, r1 = r0 + 8;
#pragma unroll
        for (int nt = 0; nt < 8; nt++) {
            int c = n_base + wn + nt * 8 + 2 * t;
            float b0 = 0.f, b1 = 0.f;
            if (bias) { b0 = bias[c]; b1 = bias[c + 1]; }
            if (r0 < M) *(float2*)(C + (size_t)r0 * N + c) =
                make_float2(acc[mt][nt][0] + b0, acc[mt][nt][1] + b1);
            if (r1 < M) *(float2*)(C + (size_t)r1 * N + c) =
                make_float2(acc[mt][nt][2] + b0, acc[mt][nt][3] + b1);
        }
    }
}

// ---------------- fused EdgeConv MLP2 + segment-max (+L2 prefetch of next A tile) ----------------
__global__ __launch_bounds__(256, 2) void edge_bf3_kernel(
    const float* __restrict__ PQ, const float* __restrict__ b1,
    const float* __restrict__ W2,
    const int* __restrict__ src, const int* __restrict__ dst,
    unsigned* __restrict__ emax, int E)
{
    extern __shared__ uint32_t smu[];
    __shared__ int se[128], de[128];
    const int tid = threadIdx.x;
    const int warp = tid >> 5, lane = tid & 31;
    const int g = lane >> 2, t = lane & 3;
    const int warp_m = warp & 3, warp_n = warp >> 2;
    const int e_base = blockIdx.y * 128;
    const int wm = warp_m * 32, wn = warp_n * 64;
    const int a_row = tid >> 3, a_c4 = (tid & 7) * 4;
    const int b_k2 = tid >> 5, b_c4 = (tid & 31) * 4;

    if (tid < 128) {
        int e = e_base + tid;
        bool ok = (e < E);
        se[tid] = ok ? src[e] : 0;
        de[tid] = ok ? dst[e] : 0;
    }
    __syncthreads();

    float acc[2][8][4];
#pragma unroll
    for (int i = 0; i < 2; i++)
#pragma unroll
        for (int j = 0; j < 8; j++)
#pragma unroll
            for (int c = 0; c < 4; c++) acc[i][j][c] = 0.f;

    float4 bv0[2], bv1[2];

#define EB_LDG(kt)                                                                 \
    {                                                                              \
        _Pragma("unroll")                                                          \
        for (int i = 0; i < 2; i++) {                                              \
            int k2 = b_k2 + i * 8;                                                 \
            bv0[i] = *(const float4*)(W2 + (size_t)((kt) + 2 * k2) * 128 + b_c4);     \
            bv1[i] = *(const float4*)(W2 + (size_t)((kt) + 2 * k2 + 1) * 128 + b_c4); \
        }                                                                          \
    }
#define EB_B_STS(st)                                                               \
    {                                                                              \
        uint32_t* sb = smu + (st) * STAGE_U;                                       \
        _Pragma("unroll")                                                          \
        for (int i = 0; i < 2; i++) STS_B4(sb, b_k2 + i * 8, b_c4, bv0[i], bv1[i]);\
    }
#define EB_A_PREF(kt)                                                              \
    {                                                                              \
        _Pragma("unroll")                                                          \
        for (int i = 0; i < 4; i++) {                                              \
            int row = a_row + i * 32;                                              \
            size_t dof = (size_t)de[row] * 1024, sof = (size_t)se[row] * 1024 + 512; \
            pref_l2(PQ + dof + (kt) + a_c4);                                       \
            pref_l2(PQ + sof + (kt) + a_c4);                                       \
        }                                                                          \
    }
#define EB_A_STS(kt, st)                                                           \
    {                                                                              \
        uint32_t* sb = smu + (st) * STAGE_U;                                       \
        float4 bb = *(const float4*)(b1 + (kt) + a_c4);                            \
        _Pragma("unroll")                                                          \
        for (int i = 0; i < 4; i++) {                                              \
            int row = a_row + i * 32;                                              \
            size_t dof = (size_t)de[row] * 1024, sof = (size_t)se[row] * 1024 + 512; \
            float4 rv = *(const float4*)(PQ + dof + (kt) + a_c4);                  \
            float4 qv = *(const float4*)(PQ + sof + (kt) + a_c4);                  \
            float4 h;                                                              \
            h.x = fmaxf(rv.x + qv.x + bb.x, 0.f);                                  \
            h.y = fmaxf(rv.y + qv.y + bb.y, 0.f);                                  \
            h.z = fmaxf(rv.z + qv.z + bb.z, 0.f);                                  \
            h.w = fmaxf(rv.w + qv.w + bb.w, 0.f);                                  \
            STS_A4(sb, row, a_c4, h);                                              \
        }                                                                          \
    }

    EB_A_STS(0, 0);
    EB_LDG(0);
    int stage = 0;
    for (int kt = 0; kt < 512; kt += 32, stage ^= 1) {
        EB_B_STS(stage);
        __syncthreads();
        if (kt + 32 < 512) {
            EB_A_PREF(kt + 32);     // warm L2 while COMPUTE runs
            EB_LDG(kt + 32);
        }
        const uint32_t* sb = smu + stage * STAGE_U;
        BF_COMPUTE(sb);
        if (kt + 32 < 512) EB_A_STS(kt + 32, stage ^ 1);
    }

#pragma unroll
    for (int mt = 0; mt < 2; mt++) {
        int r0 = wm + mt * 16 + g, r1 = r0 + 8;
        int e0 = e_base + r0, e1 = e_base + r1;
        int d0 = de[r0], d1 = de[r1];
#pragma unroll
        for (int nt = 0; nt < 8; nt++) {
            int c = wn + nt * 8 + 2 * t;
            if (e0 < E) {
                atomicMax(emax + (size_t)d0 * DIMF + c,     fkey(acc[mt][nt][0]));
                atomicMax(emax + (size_t)d0 * DIMF + c + 1, fkey(acc[mt][nt][1]));
            }
            if (e1 < E) {
                atomicMax(emax + (size_t)d1 * DIMF + c,     fkey(acc[mt][nt][2]));
                atomicMax(emax + (size_t)d1 * DIMF + c + 1, fkey(acc[mt][nt][3]));
            }
        }
    }
}

// ---------------- CSR-fused attention kernels ----------------
// online-softmax single pass: one loop gathers K and V; exact rescaling.
__global__ void trans_fused_kernel(
    const float* __restrict__ qkvs, const int* __restrict__ rowptr,
    const int* __restrict__ srcs,
    float* __restrict__ out, int n, float scale)
{
    int idx = blockIdx.x * blockDim.x + threadIdx.x;
    int d = idx >> 5, lane = idx & 31;
    if (d >= n) return;
    int beg = rowptr[d], end = rowptr[d + 1];
    if (beg == end) return;
    float4 q = *(const float4*)(qkvs + (size_t)d * 512 + lane * 4);
    float m = -INFINITY, dsum = 0.f;
    float4 acc = make_float4(0.f, 0.f, 0.f, 0.f);
    for (int e = beg; e < end; e++) {
        int s0 = srcs[e];
        if (e + 1 < end) {
            int sn = srcs[e + 1];
            pref_l2(qkvs + (size_t)sn * 512 + 128 + lane * 4);
            pref_l2(qkvs + (size_t)sn * 512 + 256 + lane * 4);
        }
        float4 kv = *(const float4*)(qkvs + (size_t)s0 * 512 + 128 + lane * 4);
        float4 vv = *(const float4*)(qkvs + (size_t)s0 * 512 + 256 + lane * 4);
        float s = q.x * kv.x + q.y * kv.y + q.z * kv.z + q.w * kv.w;
#pragma unroll
        for (int o = 16; o; o >>= 1) s += __shfl_xor_sync(0xffffffffu, s, o);
        s *= scale;
        float mn = fmaxf(m, s);
        float corr = expf(m - mn);      // exp(-inf)=0 on first iter
        float ex = expf(s - mn);
        dsum = dsum * corr + ex;
        acc.x = acc.x * corr + ex * vv.x;
        acc.y = acc.y * corr + ex * vv.y;
        acc.z = acc.z * corr + ex * vv.z;
        acc.w = acc.w * corr + ex * vv.w;
        m = mn;
    }
    float inv = 1.f / (dsum + 1e-16f);
    float* op = out + (size_t)d * DIMF + lane * 4;
    float4 o = *(float4*)op;
    o.x += acc.x * inv; o.y += acc.y * inv;
    o.z += acc.z * inv; o.w += acc.w * inv;
    *(float4*)op = o;
}

__global__ void gat_fused_kernel(
    const float* __restrict__ ss, const float* __restrict__ sd,
    const float* __restrict__ hs, const int* __restrict__ rowptr,
    const int* __restrict__ srcs, float* __restrict__ escore,
    const float* __restrict__ gb, float* __restrict__ out, int n)
{
    int idx = blockIdx.x * blockDim.x + threadIdx.x;
    int d = idx >> 5, lane = idx & 31;
    if (d >= n) return;
    float* op = out + (size_t)d * DIMF + lane * 4;
    float4 o = *(float4*)op;
    float4 bv = *(const float4*)(gb + lane * 4);
    o.x += bv.x; o.y += bv.y; o.z += bv.z; o.w += bv.w;
    int beg = rowptr[d], end = rowptr[d + 1];
    if (beg < end) {
        float sdd = sd[d];
        float m = -INFINITY;
        for (int e = beg + lane; e < end; e += 32) {
            float s = ss[srcs[e]] + sdd;
            s = (s > 0.f) ? s : 0.2f * s;
            escore[e] = s;
            m = fmaxf(m, s);
        }
#pragma unroll
        for (int oo = 16; oo; oo >>= 1) m = fmaxf(m, __shfl_xor_sync(0xffffffffu, m, oo));
        __syncwarp();
        float4 acc = make_float4(0.f, 0.f, 0.f, 0.f);
        float dsum = 0.f;
        for (int e = beg; e < end; e++) {
            if (e + 1 < end)
                pref_l2(hs + (size_t)srcs[e + 1] * DIMF + lane * 4);
            float ex = expf(escore[e] - m);
            dsum += ex;
            int s0 = srcs[e];
            float4 hv = *(const float4*)(hs + (size_t)s0 * DIMF + lane * 4);
            acc.x += ex * hv.x; acc.y += ex * hv.y;
            acc.z += ex * hv.z; acc.w += ex * hv.w;
        }
        float inv = 1.f / (dsum + 1e-16f);
        o.x += acc.x * inv; o.y += acc.y * inv;
        o.z += acc.z * inv; o.w += acc.w * inv;
    }
    *(float4*)op = o;
}

// ---------------- one-time weight prep ----------------
__global__ void concat_trans_kernel(const float* Wq, const float* Wk, const float* Wv,
                                    const float* Ws, const float* bq, const float* bk,
                                    const float* bv, const float* bs,
                                    float* Wcat, float* bcat)
{
    int i = blockIdx.x * blockDim.x + threadIdx.x;
    if (i >= 4 * 128 * 512) return;
    int inst = i >> 16, r = (i >> 9) & 127, j = i & 511;
    int sel = j >> 7, jj = j & 127;
    const float* W = sel == 0 ? Wq : sel == 1 ? Wk : sel == 2 ? Wv : Ws;
    Wcat[i] = W[((size_t)inst * 128 + r) * 128 + jj];
    if (r == 0) {
        const float* bb = sel == 0 ? bq : sel == 1 ? bk : sel == 2 ? bv : bs;
        bcat[inst * 512 + j] = bb[inst * 128 + jj];
    }
}
__global__ void concat_edge_kernel(const float* W1, float* Wcat)
{
    int i = blockIdx.x * blockDim.x + threadIdx.x;
    if (i >= 4 * 128 * 1024) return;
    int inst = i >> 17, r = (i >> 10) & 127, j = i & 1023;
    const float* Wi = W1 + (size_t)inst * 256 * 512;
    if (j < 512) Wcat[i] = Wi[(size_t)r * 512 + j] - Wi[(size_t)(128 + r) * 512 + j];
    else         Wcat[i] = Wi[(size_t)(128 + r) * 512 + (j - 512)];
}
__global__ void wadall_kernel(const float* __restrict__ gW, const float* __restrict__ gAd,
                              float* __restrict__ wad)
{
    int b = blockIdx.x, j = threadIdx.x;
    float s = 0.f;
    for (int kk = 0; kk < 128; kk++)
        s += gW[((size_t)b * 128 + j) * 128 + kk] * gAd[b * 128 + kk];
    wad[b * 128 + j] = s;
}

// ---------------- batched counting sort ----------------
__global__ void fill_i32_kernel(int* p, int val, int n) {
    int i = blockIdx.x * blockDim.x + threadIdx.x;
    if (i < n) p[i] = val;
}
__global__ void count4_kernel(const int* __restrict__ lld, const int* __restrict__ ppd,
                              const int* __restrict__ lpd, const int* __restrict__ pld,
                              int* __restrict__ hist)
{
    int e = blockIdx.x * blockDim.x + threadIdx.x;
    if (e >= E_TOT) return;
    int d;
    if (e < F_PP)      d = O_LL + lld[e];
    else if (e < F_LP) d = O_PP + ppd[e - F_PP];
    else if (e < F_PL) d = O_LP + lpd[e - F_LP];
    else               d = O_PL + pld[e - F_PL];
    atomicAdd(hist + d, 1);
}
__global__ void scan1_kernel(const int* __restrict__ hist, int* __restrict__ off,
                             int* __restrict__ bsum, int n) {
    __shared__ int sh[SCAN_B];
    int tid = threadIdx.x, i = blockIdx.x * SCAN_B + tid;
    int v = (i < n) ? hist[i] : 0;
    sh[tid] = v; __syncthreads();
    for (int d = 1; d < SCAN_B; d <<= 1) {
        int t2 = (tid >= d) ? sh[tid - d] : 0;
        __syncthreads(); sh[tid] += t2; __syncthreads();
    }
    if (i < n) off[i] = sh[tid] - v;
    if (tid == SCAN_B - 1) bsum[blockIdx.x] = sh[tid];
}
__global__ void scan2_kernel(int* __restrict__ bsum, int nb) {
    __shared__ int sh[SCAN_B];
    int tid = threadIdx.x;
    int v = (tid < nb) ? bsum[tid] : 0;
    sh[tid] = v; __syncthreads();
    for (int d = 1; d < SCAN_B; d <<= 1) {
        int t2 = (tid >= d) ? sh[tid - d] : 0;
        __syncthreads(); sh[tid] += t2; __syncthreads();
    }
    if (tid < nb) bsum[tid] = sh[tid] - v;
}
__global__ void scan3_kernel(const int* __restrict__ off, const int* __restrict__ bsum,
                             int* __restrict__ work,
                             int* __restrict__ rp_ll, int* __restrict__ rp_lp,
                             int* __restrict__ rp_pl)
{
    int i = blockIdx.x * blockDim.x + threadIdx.x;
    if (i < NT_NODES) {
        int v = off[i] + bsum[i / SCAN_B];
        work[i] = v;
        if (i < O_PP)                       rp_ll[i] = v - F_LL;
        else if (i >= O_LP && i < O_PL)     rp_lp[i - O_LP] = v - F_LP;
        else if (i >= O_PL)                 rp_pl[i - O_PL] = v - F_PL;
    }
    if (i == 0) {
        rp_ll[N_LEGO]  = NE_LL;
        rp_lp[N_POINT] = NE_LP;
        rp_pl[N_LEGO]  = NE_PL;
    }
}
__global__ void scatter4_kernel(
    const int* __restrict__ lls, const int* __restrict__ lld,
    const int* __restrict__ pps, const int* __restrict__ ppd,
    const int* __restrict__ lps, const int* __restrict__ lpd,
    const int* __restrict__ pls, const int* __restrict__ pld,
    int* __restrict__ work,
    int* __restrict__ oll, int* __restrict__ opp_s, int* __restrict__ opp_d,
    int* __restrict__ olp, int* __restrict__ opl)
{
    int e = blockIdx.x * blockDim.x + threadIdx.x;
    if (e >= E_TOT) return;
    if (e < F_PP) {
        int d = lld[e];
        int pos = atomicAdd(work + O_LL + d, 1);
        oll[pos - F_LL] = lls[e];
    } else if (e < F_LP) {
        int el = e - F_PP;
        int d = ppd[el];
        int pos = atomicAdd(work + O_PP + d, 1) - F_PP;
        opp_s[pos] = pps[el];
        opp_d[pos] = d;
    } else if (e < F_PL) {
        int el = e - F_LP;
        int d = lpd[el];
        int pos = atomicAdd(work + O_LP + d, 1);
        olp[pos - F_LP] = lps[el];
    } else {
        int el = e - F_PL;
        int d = pld[el];
        int pos = atomicAdd(work + O_PL + d, 1);
        opl[pos - F_PL] = pls[el];
    }
}

// ---------------- small glue kernels ----------------
__global__ void fill_u32_kernel(unsigned* p, unsigned val, int n) {
    int i = blockIdx.x * blockDim.x + threadIdx.x;
    if (i < n) p[i] = val;
}
__global__ void copy_skip_kernel(const float* __restrict__ qkvs, float* __restrict__ out, int n) {
    int i = blockIdx.x * blockDim.x + threadIdx.x;
    if (i >= n * 32) return;
    int row = i >> 5, f = (i & 31) * 4;
    *(float4*)(out + (size_t)row * DIMF + f) =
        *(const float4*)(qkvs + (size_t)row * 512 + 384 + f);
}
__global__ void node_dot_kernel(const float* __restrict__ h, const float* __restrict__ avec,
                                float* __restrict__ out, int n)
{
    int idx = blockIdx.x * blockDim.x + threadIdx.x;
    int i = idx >> 5, lane = idx & 31;
    if (i >= n) return;
    float4 hv = *(const float4*)(h + (size_t)i * DIMF + lane * 4);
    float4 av = *(const float4*)(avec + lane * 4);
    float s = hv.x * av.x + hv.y * av.y + hv.z * av.z + hv.w * av.w;
#pragma unroll
    for (int o = 16; o; o >>= 1) s += __shfl_xor_sync(0xffffffffu, s, o);
    if (lane == 0) out[i] = s;
}
__global__ void finalize_max_b2_kernel(unsigned* __restrict__ emax,
                                       const float* __restrict__ b2,
                                       float* __restrict__ out, int total) {
    int i = blockIdx.x * blockDim.x + threadIdx.x;
    if (i >= total) return;
    float v = fdecode(emax[i]);
    out[i] = isfinite(v) ? v + b2[i & (DIMF - 1)] : 0.f;
    emax[i] = NEG_INF_KEY;
}

// ---------------- host orchestration ----------------
static inline int div_up(int a, int b) { return (a + b - 1) / b; }

struct Scratch {
    float *xl, *xp, *la, *pa, *hs, *ss, *sd, *escore, *PQ;
    float *WcatT, *bcatT, *WcatE, *wadall;
    unsigned *emax;
    int *hist4, *work4, *bsum;
    int *sll_s, *spp_s, *spp_d, *slp_s, *spl_s;
    int *rp_ll, *rp_lp, *rp_pl;
};

static void sgemm(const float* A, const float* B, const float* bias, float* C,
                  int M, int N, int K) {
    dim3 grid(N / 128, div_up(M, 128));
    bf3_gemm_kernel<<<grid, 256, SMEM_BYTES>>>(A, B, bias, C, M, N, K);
}

static void run_trans(const Scratch& S, const float* x, int n, int inst,
                      const int* rowptr, const int* srcs, float* out)
{
    sgemm(x, S.WcatT + (size_t)inst * 128 * 512, S.bcatT + inst * 512, S.PQ, n, 512, DIMF);
    copy_skip_kernel<<<div_up(n * 32, 256), 256>>>(S.PQ, out, n);
    float scale = 1.f / sqrtf((float)DIMF);
    trans_fused_kernel<<<div_up(n * 32, 256), 256>>>(S.PQ, rowptr, srcs, out, n, scale);
}

static void run_gat(const Scratch& S, const float* xs, int ns, const float* xd, int nd,
                    const int* rowptr, const int* srcs, int inst,
                    const float* W, const float* a_src, const float* gb, float* out)
{
    sgemm(xs, W, nullptr, S.hs, ns, DIMF, DIMF);
    node_dot_kernel<<<div_up(ns * 32, 256), 256>>>(S.hs, a_src, S.ss, ns);
    node_dot_kernel<<<div_up(nd * 32, 256), 256>>>(xd, S.wadall + inst * 128, S.sd, nd);
    gat_fused_kernel<<<div_up(nd * 32, 256), 256>>>(S.ss, S.sd, S.hs, rowptr, srcs,
                                                    S.escore, gb, out, nd);
}

static void run_edge(const Scratch& S, const float* x, int n, int inst,
                     const int* src, const int* dst, int E,
                     const float* b1, const float* W2, const float* b2, float* out)
{
    sgemm(x, S.WcatE + (size_t)inst * 128 * 1024, nullptr, S.PQ, n, 1024, DIMF);
    dim3 grid(1, div_up(E, 128));
    edge_bf3_kernel<<<grid, 256, SMEM_BYTES>>>(S.PQ, b1, W2, src, dst, S.emax, E);
    finalize_max_b2_kernel<<<div_up(n * DIMF, 256), 256>>>(S.emax, b2, out, n * DIMF);
}

extern "C" void kernel_launch(void* const* d_in, const int* in_sizes, int n_in,
                              void* d_out, int out_size)
{
    const float* x_lego  = (const float*)d_in[0];
    const float* x_point = (const float*)d_in[1];
    const float* tWq = (const float*)d_in[2];
    const float* tbq = (const float*)d_in[3];
    const float* tWk = (const float*)d_in[4];
    const float* tbk = (const float*)d_in[5];
    const float* tWv = (const float*)d_in[6];
    const float* tbv = (const float*)d_in[7];
    const float* tWs = (const float*)d_in[8];
    const float* tbs = (const float*)d_in[9];
    const float* eW1 = (const float*)d_in[10];
    const float* eb1 = (const float*)d_in[11];
    const float* eW2 = (const float*)d_in[12];
    const float* eb2 = (const float*)d_in[13];
    const float* gW  = (const float*)d_in[14];
    const float* gAs = (const float*)d_in[15];
    const float* gAd = (const float*)d_in[16];
    const float* gb  = (const float*)d_in[17];
    const int* ll_src = (const int*)d_in[18];
    const int* ll_dst = (const int*)d_in[19];
    const int* pp_src = (const int*)d_in[20];
    const int* pp_dst = (const int*)d_in[21];
    const int* lp_src = (const int*)d_in[22];
    const int* lp_dst = (const int*)d_in[23];
    const int* pl_src = (const int*)d_in[24];
    const int* pl_dst = (const int*)d_in[25];

    cudaFuncSetAttribute(bf3_gemm_kernel, cudaFuncAttributeMaxDynamicSharedMemorySize,
                         SMEM_BYTES);
    cudaFuncSetAttribute(edge_bf3_kernel, cudaFuncAttributeMaxDynamicSharedMemorySize,
                         SMEM_BYTES);

    Scratch S;
    cudaGetSymbolAddress((void**)&S.xl, g_xl);
    cudaGetSymbolAddress((void**)&S.xp, g_xp);
    cudaGetSymbolAddress((void**)&S.la, g_la);
    cudaGetSymbolAddress((void**)&S.pa, g_pa);
    cudaGetSymbolAddress((void**)&S.hs, g_hs);
    cudaGetSymbolAddress((void**)&S.ss, g_ss);
    cudaGetSymbolAddress((void**)&S.sd, g_sd);
    cudaGetSymbolAddress((void**)&S.escore, g_escore);
    cudaGetSymbolAddress((void**)&S.PQ, g_PQ);
    cudaGetSymbolAddress((void**)&S.emax, g_emax);
    cudaGetSymbolAddress((void**)&S.WcatT, g_WcatT);
    cudaGetSymbolAddress((void**)&S.bcatT, g_bcatT);
    cudaGetSymbolAddress((void**)&S.WcatE, g_WcatE);
    cudaGetSymbolAddress((void**)&S.wadall, g_wadall);
    cudaGetSymbolAddress((void**)&S.hist4, g_hist4);
    cudaGetSymbolAddress((void**)&S.work4, g_work4);
    cudaGetSymbolAddress((void**)&S.bsum, g_bsum);
    cudaGetSymbolAddress((void**)&S.sll_s, g_sll_s);
    cudaGetSymbolAddress((void**)&S.spp_s, g_spp_s);
    cudaGetSymbolAddress((void**)&S.spp_d, g_spp_d);
    cudaGetSymbolAddress((void**)&S.slp_s, g_slp_s);
    cudaGetSymbolAddress((void**)&S.spl_s, g_spl_s);
    cudaGetSymbolAddress((void**)&S.rp_ll, g_rp_ll);
    cudaGetSymbolAddress((void**)&S.rp_lp, g_rp_lp);
    cudaGetSymbolAddress((void**)&S.rp_pl, g_rp_pl);

    cudaMemcpyAsync(S.xl, x_lego,  (size_t)N_LEGO * DIMF * sizeof(float),  cudaMemcpyDeviceToDevice);
    cudaMemcpyAsync(S.xp, x_point, (size_t)N_POINT * DIMF * sizeof(float), cudaMemcpyDeviceToDevice);

    concat_trans_kernel<<<div_up(4 * 128 * 512, 256), 256>>>(tWq, tWk, tWv, tWs,
                                                             tbq, tbk, tbv, tbs,
                                                             S.WcatT, S.bcatT);
    concat_edge_kernel<<<div_up(4 * 128 * 1024, 256), 256>>>(eW1, S.WcatE);
    wadall_kernel<<<4, 128>>>(gW, gAd, S.wadall);
    fill_u32_kernel<<<div_up(N_POINT * DIMF, 256), 256>>>(S.emax, NEG_INF_KEY, N_POINT * DIMF);

    fill_i32_kernel<<<div_up(NT_NODES, 256), 256>>>(S.hist4, 0, NT_NODES);
    count4_kernel<<<div_up(E_TOT, 256), 256>>>(ll_dst, pp_dst, lp_dst, pl_dst, S.hist4);
    int nb = div_up(NT_NODES, SCAN_B);
    scan1_kernel<<<nb, SCAN_B>>>(S.hist4, S.work4, S.bsum, NT_NODES);
    scan2_kernel<<<1, SCAN_B>>>(S.bsum, nb);
    scan3_kernel<<<div_up(NT_NODES, 256), 256>>>(S.work4, S.bsum, S.hist4,
                                                 S.rp_ll, S.rp_lp, S.rp_pl);
    scatter4_kernel<<<div_up(E_TOT, 256), 256>>>(ll_src, ll_dst, pp_src, pp_dst,
                                                 lp_src, lp_dst, pl_src, pl_dst,
                                                 S.hist4, S.sll_s, S.spp_s, S.spp_d,
                                                 S.slp_s, S.spl_s);

    for (int layer = 0; layer < 2; layer++) {
        int iA = 2 * layer, iB = 2 * layer + 1;
        int i_lp = 2 * layer, i_pl = 2 * layer + 1;

        run_trans(S, S.xl, N_LEGO, iA, S.rp_ll, S.sll_s, S.la);
        run_gat(S, S.xp, N_POINT, S.xl, N_LEGO, S.rp_pl, S.spl_s, i_pl,
                gW + i_pl * DIMF * DIMF, gAs + i_pl * DIMF, gb + i_pl * DIMF, S.la);

        run_edge(S, S.xp, N_POINT, iA, S.spp_s, S.spp_d, NE_PP,
                 eb1 + iA * 512, eW2 + (size_t)iA * 512 * DIMF, eb2 + iA * DIMF, S.pa);
        run_gat(S, S.xl, N_LEGO, S.xp, N_POINT, S.rp_lp, S.slp_s, i_lp,
                gW + i_lp * DIMF * DIMF, gAs + i_lp * DIMF, gb + i_lp * DIMF, S.pa);

        run_trans(S, S.la, N_LEGO, iB, S.rp_ll, S.sll_s, S.xl);
        run_edge(S, S.pa, N_POINT, iB, S.spp_s, S.spp_d, NE_PP,
                 eb1 + iB * 512, eW2 + (size_t)iB * 512 * DIMF, eb2 + iB * DIMF, S.xp);
    }

    float* out = (float*)d_out;
    cudaMemcpyAsync(out, S.xl, (size_t)N_LEGO * DIMF * sizeof(float), cudaMemcpyDeviceToDevice);
    cudaMemcpyAsync(out + (size_t)N_LEGO * DIMF, S.xp, (size_t)N_POINT * DIMF * sizeof(float),
                    cudaMemcpyDeviceToDevice);
}

// round 17
// speedup vs baseline: 1.1575x; 1.0078x over previous
#include <cuda_runtime.h>
#include <math.h>
#include <stdint.h>

#define DIMF 128
#define N_LEGO 50000
#define N_POINT 100000
#define NE_LL 500000
#define NE_PP 400000
#define NE_LP 500000
#define NE_PL 500000
#define NEG_INF_KEY 0x007FFFFFu
#define SCAN_B 1024
#define O_LL 0
#define O_PP N_LEGO
#define O_LP (N_LEGO + N_POINT)
#define O_PL (N_LEGO + 2 * N_POINT)
#define NT_NODES (2 * N_LEGO + 2 * N_POINT)
#define F_LL 0
#define F_PP NE_LL
#define F_LP (NE_LL + NE_PP)
#define F_PL (NE_LL + NE_PP + NE_LP)
#define E_TOT (NE_LL + NE_PP + NE_LP + NE_PL)

// ---------------- scratch ----------------
__device__ float    g_xl[N_LEGO * DIMF];
__device__ float    g_xp[N_POINT * DIMF];
__device__ float    g_la[N_LEGO * DIMF];
__device__ float    g_pa[N_POINT * DIMF];
__device__ float    g_hs[N_POINT * DIMF];
__device__ float    g_ss[N_POINT];
__device__ float    g_sd[N_POINT];
__device__ float    g_escore[NE_LL];
__device__ float    g_PQ[(size_t)N_POINT * 1024];
__device__ unsigned g_emax[N_POINT * DIMF];
__device__ float    g_WcatT[4 * 128 * 512];
__device__ float    g_bcatT[4 * 512];
__device__ float    g_WcatE[4 * 128 * 1024];
__device__ float    g_wadall[4 * 128];
__device__ int g_hist4[NT_NODES], g_work4[NT_NODES], g_bsum[SCAN_B];
__device__ int g_sll_s[NE_LL];
__device__ int g_spp_s[NE_PP], g_spp_d[NE_PP];
__device__ int g_slp_s[NE_LP];
__device__ int g_spl_s[NE_PL];
__device__ int g_rp_ll[N_LEGO + 1], g_rp_lp[N_POINT + 1], g_rp_pl[N_LEGO + 1];

// ---------------- helpers ----------------
__device__ __forceinline__ unsigned fkey(float f) {
    unsigned u = __float_as_uint(f);
    return (u & 0x80000000u) ? ~u : (u | 0x80000000u);
}
__device__ __forceinline__ float fdecode(unsigned kk) {
    unsigned u = (kk & 0x80000000u) ? (kk ^ 0x80000000u) : ~kk;
    return __uint_as_float(u);
}
__device__ __forceinline__ uint2 bfsplit2(float v0, float v1) {
    uint32_t h, m;
    asm("cvt.rn.bf16x2.f32 %0, %1, %2;" : "=r"(h) : "f"(v1), "f"(v0));
    float h0 = __uint_as_float(h << 16);
    float h1 = __uint_as_float(h & 0xffff0000u);
    asm("cvt.rn.bf16x2.f32 %0, %1, %2;" : "=r"(m) : "f"(v1 - h1), "f"(v0 - h0));
    return make_uint2(h, m);
}
__device__ __forceinline__ void pref_l2(const void* p) {
    asm volatile("prefetch.global.L2 [%0];" :: "l"(p));
}

// ---------------- GEMM (round-7/8 WIN, unchanged) ----------------
#define AHS 20
#define BHS 136
#define AH_OFF 0
#define AM_OFF 2560
#define BH_OFF 5120
#define BM_OFF 7296
#define STAGE_U 9472
#define SMEM_BYTES (2 * STAGE_U * 4)

#define MMA_BF16(accv, a0, a1, a2, a3, b0, b1)                                     \
    asm("mma.sync.aligned.m16n8k16.row.col.f32.bf16.bf16.f32 "                     \
        "{%0,%1,%2,%3}, {%4,%5,%6,%7}, {%8,%9}, {%0,%1,%2,%3};"                    \
        : "+f"(accv[0]), "+f"(accv[1]), "+f"(accv[2]), "+f"(accv[3])               \
        : "r"(a0), "r"(a1), "r"(a2), "r"(a3), "r"(b0), "r"(b1))

#define BF_COMPUTE(sb)                                                             \
    {                                                                              \
        _Pragma("unroll")                                                          \
        for (int kc = 0; kc < 2; kc++) {                                           \
            uint32_t ah[2][4], am[2][4];                                           \
            _Pragma("unroll")                                                      \
            for (int mt = 0; mt < 2; mt++) {                                       \
                int r0 = wm + mt * 16 + g;                                         \
                int o0 = r0 * AHS + kc * 8 + t, o1 = (r0 + 8) * AHS + kc * 8 + t;  \
                ah[mt][0] = (sb)[AH_OFF + o0];     ah[mt][1] = (sb)[AH_OFF + o1];  \
                ah[mt][2] = (sb)[AH_OFF + o0 + 4]; ah[mt][3] = (sb)[AH_OFF + o1 + 4]; \
                am[mt][0] = (sb)[AM_OFF + o0];     am[mt][1] = (sb)[AM_OFF + o1];  \
                am[mt][2] = (sb)[AM_OFF + o0 + 4]; am[mt][3] = (sb)[AM_OFF + o1 + 4]; \
            }                                                                      \
            _Pragma("unroll")                                                      \
            for (int nt = 0; nt < 8; nt++) {                                       \
                int nn = wn + nt * 8 + g;                                          \
                int p0 = (kc * 8 + t) * BHS + nn, p1 = (kc * 8 + t + 4) * BHS + nn;\
                uint32_t b0h = (sb)[BH_OFF + p0], b1h = (sb)[BH_OFF + p1];         \
                uint32_t b0m = (sb)[BM_OFF + p0], b1m = (sb)[BM_OFF + p1];         \
                _Pragma("unroll")                                                  \
                for (int mt = 0; mt < 2; mt++) {                                   \
                    MMA_BF16(acc[mt][nt], am[mt][0], am[mt][1], am[mt][2],         \
                             am[mt][3], b0h, b1h);                                 \
                    MMA_BF16(acc[mt][nt], ah[mt][0], ah[mt][1], ah[mt][2],         \
                             ah[mt][3], b0m, b1m);                                 \
                    MMA_BF16(acc[mt][nt], ah[mt][0], ah[mt][1], ah[mt][2],         \
                             ah[mt][3], b0h, b1h);                                 \
                }                                                                  \
            }                                                                      \
        }                                                                          \
    }

#define STS_A4(sb, row, c4, v4)                                                    \
    {                                                                              \
        int k2c = (c4) >> 1;                                                       \
        uint2 p01 = bfsplit2((v4).x, (v4).y);                                      \
        uint2 p23 = bfsplit2((v4).z, (v4).w);                                      \
        *(uint2*)((sb) + AH_OFF + (row) * AHS + k2c) = make_uint2(p01.x, p23.x);   \
        *(uint2*)((sb) + AM_OFF + (row) * AHS + k2c) = make_uint2(p01.y, p23.y);   \
    }
#define STS_B4(sb, k2, c4, v0, v1)                                                 \
    {                                                                              \
        uint2 q0 = bfsplit2((v0).x, (v1).x);                                       \
        uint2 q1 = bfsplit2((v0).y, (v1).y);                                       \
        uint2 q2 = bfsplit2((v0).z, (v1).z);                                       \
        uint2 q3 = bfsplit2((v0).w, (v1).w);                                       \
        *(uint4*)((sb) + BH_OFF + (k2) * BHS + (c4)) = make_uint4(q0.x, q1.x, q2.x, q3.x); \
        *(uint4*)((sb) + BM_OFF + (k2) * BHS + (c4)) = make_uint4(q0.y, q1.y, q2.y, q3.y); \
    }

__global__ __launch_bounds__(256, 2) void bf3_gemm_kernel(
    const float* __restrict__ A, const float* __restrict__ B,
    const float* __restrict__ bias, float* __restrict__ C,
    int M, int N, int K)
{
    extern __shared__ uint32_t smu[];
    const int tid = threadIdx.x;
    const int warp = tid >> 5, lane = tid & 31;
    const int g = lane >> 2, t = lane & 3;
    const int warp_m = warp & 3, warp_n = warp >> 2;
    const int m_base = blockIdx.y * 128, n_base = blockIdx.x * 128;
    const int wm = warp_m * 32, wn = warp_n * 64;
    const int a_row = tid >> 3, a_c4 = (tid & 7) * 4;
    const int b_k2 = tid >> 5, b_c4 = (tid & 31) * 4;

    float acc[2][8][4];
#pragma unroll
    for (int i = 0; i < 2; i++)
#pragma unroll
        for (int j = 0; j < 8; j++)
#pragma unroll
            for (int c = 0; c < 4; c++) acc[i][j][c] = 0.f;

    float4 av[4], bv0[2], bv1[2];
    const float4 f4z = make_float4(0.f, 0.f, 0.f, 0.f);

#define GEN_LDG(kt)                                                                \
    {                                                                              \
        _Pragma("unroll")                                                          \
        for (int i = 0; i < 4; i++) {                                              \
            int row = a_row + i * 32, gr = m_base + row;                           \
            av[i] = (gr < M) ? *(const float4*)(A + (size_t)gr * K + (kt) + a_c4)  \
                             : f4z;                                                \
        }                                                                          \
        _Pragma("unroll")                                                          \
        for (int i = 0; i < 2; i++) {                                              \
            int k2 = b_k2 + i * 8;                                                 \
            bv0[i] = *(const float4*)(B + (size_t)((kt) + 2 * k2) * N + n_base + b_c4);     \
            bv1[i] = *(const float4*)(B + (size_t)((kt) + 2 * k2 + 1) * N + n_base + b_c4); \
        }                                                                          \
    }
#define GEN_STS(st)                                                                \
    {                                                                              \
        uint32_t* sb = smu + (st) * STAGE_U;                                       \
        _Pragma("unroll")                                                          \
        for (int i = 0; i < 4; i++) STS_A4(sb, a_row + i * 32, a_c4, av[i]);       \
        _Pragma("unroll")                                                          \
        for (int i = 0; i < 2; i++) STS_B4(sb, b_k2 + i * 8, b_c4, bv0[i], bv1[i]);\
    }

    GEN_LDG(0);
    int stage = 0;
    for (int kt = 0; kt < K; kt += 32, stage ^= 1) {
        GEN_STS(stage);
        __syncthreads();
        if (kt + 32 < K) GEN_LDG(kt + 32);
        const uint32_t* sb = smu + stage * STAGE_U;
        BF_COMPUTE(sb);
    }

#pragma unroll
    for (int mt = 0; mt < 2; mt++) {
        int r0 = m_base + wm + mt * 16 + g, r1 = r0 + 8;
#pragma unroll
        for (int nt = 0; nt < 8; nt++) {
            int c = n_base + wn + nt * 8 + 2 * t;
            float b0 = 0.f, b1 = 0.f;
            if (bias) { b0 = bias[c]; b1 = bias[c + 1]; }
            if (r0 < M) *(float2*)(C + (size_t)r0 * N + c) =
                make_float2(acc[mt][nt][0] + b0, acc[mt][nt][1] + b1);
            if (r1 < M) *(float2*)(C + (size_t)r1 * N + c) =
                make_float2(acc[mt][nt][2] + b0, acc[mt][nt][3] + b1);
        }
    }
}

// ---------------- fused EdgeConv MLP2 + segment-max (round-16 WIN, unchanged) ----------------
__global__ __launch_bounds__(256, 2) void edge_bf3_kernel(
    const float* __restrict__ PQ, const float* __restrict__ b1,
    const float* __restrict__ W2,
    const int* __restrict__ src, const int* __restrict__ dst,
    unsigned* __restrict__ emax, int E)
{
    extern __shared__ uint32_t smu[];
    __shared__ int se[128], de[128];
    const int tid = threadIdx.x;
    const int warp = tid >> 5, lane = tid & 31;
    const int g = lane >> 2, t = lane & 3;
    const int warp_m = warp & 3, warp_n = warp >> 2;
    const int e_base = blockIdx.y * 128;
    const int wm = warp_m * 32, wn = warp_n * 64;
    const int a_row = tid >> 3, a_c4 = (tid & 7) * 4;
    const int b_k2 = tid >> 5, b_c4 = (tid & 31) * 4;

    if (tid < 128) {
        int e = e_base + tid;
        bool ok = (e < E);
        se[tid] = ok ? src[e] : 0;
        de[tid] = ok ? dst[e] : 0;
    }
    __syncthreads();

    float acc[2][8][4];
#pragma unroll
    for (int i = 0; i < 2; i++)
#pragma unroll
        for (int j = 0; j < 8; j++)
#pragma unroll
            for (int c = 0; c < 4; c++) acc[i][j][c] = 0.f;

    float4 bv0[2], bv1[2];

#define EB_LDG(kt)                                                                 \
    {                                                                              \
        _Pragma("unroll")                                                          \
        for (int i = 0; i < 2; i++) {                                              \
            int k2 = b_k2 + i * 8;                                                 \
            bv0[i] = *(const float4*)(W2 + (size_t)((kt) + 2 * k2) * 128 + b_c4);     \
            bv1[i] = *(const float4*)(W2 + (size_t)((kt) + 2 * k2 + 1) * 128 + b_c4); \
        }                                                                          \
    }
#define EB_B_STS(st)                                                               \
    {                                                                              \
        uint32_t* sb = smu + (st) * STAGE_U;                                       \
        _Pragma("unroll")                                                          \
        for (int i = 0; i < 2; i++) STS_B4(sb, b_k2 + i * 8, b_c4, bv0[i], bv1[i]);\
    }
#define EB_A_PREF(kt)                                                              \
    {                                                                              \
        _Pragma("unroll")                                                          \
        for (int i = 0; i < 4; i++) {                                              \
            int row = a_row + i * 32;                                              \
            size_t dof = (size_t)de[row] * 1024, sof = (size_t)se[row] * 1024 + 512; \
            pref_l2(PQ + dof + (kt) + a_c4);                                       \
            pref_l2(PQ + sof + (kt) + a_c4);                                       \
        }                                                                          \
    }
#define EB_A_STS(kt, st)                                                           \
    {                                                                              \
        uint32_t* sb = smu + (st) * STAGE_U;                                       \
        float4 bb = *(const float4*)(b1 + (kt) + a_c4);                            \
        _Pragma("unroll")                                                          \
        for (int i = 0; i < 4; i++) {                                              \
            int row = a_row + i * 32;                                              \
            size_t dof = (size_t)de[row] * 1024, sof = (size_t)se[row] * 1024 + 512; \
            float4 rv = *(const float4*)(PQ + dof + (kt) + a_c4);                  \
            float4 qv = *(const float4*)(PQ + sof + (kt) + a_c4);                  \
            float4 h;                                                              \
            h.x = fmaxf(rv.x + qv.x + bb.x, 0.f);                                  \
            h.y = fmaxf(rv.y + qv.y + bb.y, 0.f);                                  \
            h.z = fmaxf(rv.z + qv.z + bb.z, 0.f);                                  \
            h.w = fmaxf(rv.w + qv.w + bb.w, 0.f);                                  \
            STS_A4(sb, row, a_c4, h);                                              \
        }                                                                          \
    }

    EB_A_STS(0, 0);
    EB_LDG(0);
    int stage = 0;
    for (int kt = 0; kt < 512; kt += 32, stage ^= 1) {
        EB_B_STS(stage);
        __syncthreads();
        if (kt + 32 < 512) {
            EB_A_PREF(kt + 32);
            EB_LDG(kt + 32);
        }
        const uint32_t* sb = smu + stage * STAGE_U;
        BF_COMPUTE(sb);
        if (kt + 32 < 512) EB_A_STS(kt + 32, stage ^ 1);
    }

#pragma unroll
    for (int mt = 0; mt < 2; mt++) {
        int r0 = wm + mt * 16 + g, r1 = r0 + 8;
        int e0 = e_base + r0, e1 = e_base + r1;
        int d0 = de[r0], d1 = de[r1];
#pragma unroll
        for (int nt = 0; nt < 8; nt++) {
            int c = wn + nt * 8 + 2 * t;
            if (e0 < E) {
                atomicMax(emax + (size_t)d0 * DIMF + c,     fkey(acc[mt][nt][0]));
                atomicMax(emax + (size_t)d0 * DIMF + c + 1, fkey(acc[mt][nt][1]));
            }
            if (e1 < E) {
                atomicMax(emax + (size_t)d1 * DIMF + c,     fkey(acc[mt][nt][2]));
                atomicMax(emax + (size_t)d1 * DIMF + c + 1, fkey(acc[mt][nt][3]));
            }
        }
    }
}

// ---------------- CSR-fused attention kernels ----------------
// online softmax, software-pipelined K/V loads, skip folded in (writes out once)
__global__ void trans_fused_kernel(
    const float* __restrict__ qkvs, const int* __restrict__ rowptr,
    const int* __restrict__ srcs,
    float* __restrict__ out, int n, float scale)
{
    int idx = blockIdx.x * blockDim.x + threadIdx.x;
    int d = idx >> 5, lane = idx & 31;
    if (d >= n) return;
    float4 o = *(const float4*)(qkvs + (size_t)d * 512 + 384 + lane * 4);  // skip
    int beg = rowptr[d], end = rowptr[d + 1];
    if (beg < end) {
        float4 q = *(const float4*)(qkvs + (size_t)d * 512 + lane * 4);
        float m = -INFINITY, dsum = 0.f;
        float4 acc = make_float4(0.f, 0.f, 0.f, 0.f);
        int s0 = srcs[beg];
        float4 kv = *(const float4*)(qkvs + (size_t)s0 * 512 + 128 + lane * 4);
        float4 vv = *(const float4*)(qkvs + (size_t)s0 * 512 + 256 + lane * 4);
        for (int e = beg; e < end; e++) {
            float4 kc = kv, vc = vv;
            if (e + 1 < end) {
                int sn = srcs[e + 1];
                if (e + 2 < end) {
                    int sp = srcs[e + 2];
                    pref_l2(qkvs + (size_t)sp * 512 + 128 + lane * 4);
                    pref_l2(qkvs + (size_t)sp * 512 + 256 + lane * 4);
                }
                kv = *(const float4*)(qkvs + (size_t)sn * 512 + 128 + lane * 4);
                vv = *(const float4*)(qkvs + (size_t)sn * 512 + 256 + lane * 4);
            }
            float s = q.x * kc.x + q.y * kc.y + q.z * kc.z + q.w * kc.w;
#pragma unroll
            for (int oo = 16; oo; oo >>= 1) s += __shfl_xor_sync(0xffffffffu, s, oo);
            s *= scale;
            float mn = fmaxf(m, s);
            float corr = expf(m - mn);
            float ex = expf(s - mn);
            dsum = dsum * corr + ex;
            acc.x = acc.x * corr + ex * vc.x;
            acc.y = acc.y * corr + ex * vc.y;
            acc.z = acc.z * corr + ex * vc.z;
            acc.w = acc.w * corr + ex * vc.w;
            m = mn;
        }
        float inv = 1.f / (dsum + 1e-16f);
        o.x += acc.x * inv; o.y += acc.y * inv;
        o.z += acc.z * inv; o.w += acc.w * inv;
    }
    *(float4*)(out + (size_t)d * DIMF + lane * 4) = o;
}

__global__ void gat_fused_kernel(
    const float* __restrict__ ss, const float* __restrict__ sd,
    const float* __restrict__ hs, const int* __restrict__ rowptr,
    const int* __restrict__ srcs, float* __restrict__ escore,
    const float* __restrict__ gb, float* __restrict__ out, int n)
{
    int idx = blockIdx.x * blockDim.x + threadIdx.x;
    int d = idx >> 5, lane = idx & 31;
    if (d >= n) return;
    float* op = out + (size_t)d * DIMF + lane * 4;
    float4 o = *(float4*)op;
    float4 bv = *(const float4*)(gb + lane * 4);
    o.x += bv.x; o.y += bv.y; o.z += bv.z; o.w += bv.w;
    int beg = rowptr[d], end = rowptr[d + 1];
    if (beg < end) {
        float sdd = sd[d];
        float m = -INFINITY;
        for (int e = beg + lane; e < end; e += 32) {
            float s = ss[srcs[e]] + sdd;
            s = (s > 0.f) ? s : 0.2f * s;
            escore[e] = s;
            m = fmaxf(m, s);
        }
#pragma unroll
        for (int oo = 16; oo; oo >>= 1) m = fmaxf(m, __shfl_xor_sync(0xffffffffu, m, oo));
        __syncwarp();
        float4 acc = make_float4(0.f, 0.f, 0.f, 0.f);
        float dsum = 0.f;
        float4 hv = *(const float4*)(hs + (size_t)srcs[beg] * DIMF + lane * 4);
        for (int e = beg; e < end; e++) {
            float4 hc = hv;
            if (e + 1 < end) {
                int sn = srcs[e + 1];
                if (e + 2 < end)
                    pref_l2(hs + (size_t)srcs[e + 2] * DIMF + lane * 4);
                hv = *(const float4*)(hs + (size_t)sn * DIMF + lane * 4);
            }
            float ex = expf(escore[e] - m);
            dsum += ex;
            acc.x += ex * hc.x; acc.y += ex * hc.y;
            acc.z += ex * hc.z; acc.w += ex * hc.w;
        }
        float inv = 1.f / (dsum + 1e-16f);
        o.x += acc.x * inv; o.y += acc.y * inv;
        o.z += acc.z * inv; o.w += acc.w * inv;
    }
    *(float4*)op = o;
}

// ---------------- one-time weight prep ----------------
__global__ void concat_trans_kernel(const float* Wq, const float* Wk, const float* Wv,
                                    const float* Ws, const float* bq, const float* bk,
                                    const float* bv, const float* bs,
                                    float* Wcat, float* bcat)
{
    int i = blockIdx.x * blockDim.x + threadIdx.x;
    if (i >= 4 * 128 * 512) return;
    int inst = i >> 16, r = (i >> 9) & 127, j = i & 511;
    int sel = j >> 7, jj = j & 127;
    const float* W = sel == 0 ? Wq : sel == 1 ? Wk : sel == 2 ? Wv : Ws;
    Wcat[i] = W[((size_t)inst * 128 + r) * 128 + jj];
    if (r == 0) {
        const float* bb = sel == 0 ? bq : sel == 1 ? bk : sel == 2 ? bv : bs;
        bcat[inst * 512 + j] = bb[inst * 128 + jj];
    }
}
__global__ void concat_edge_kernel(const float* W1, float* Wcat)
{
    int i = blockIdx.x * blockDim.x + threadIdx.x;
    if (i >= 4 * 128 * 1024) return;
    int inst = i >> 17, r = (i >> 10) & 127, j = i & 1023;
    const float* Wi = W1 + (size_t)inst * 256 * 512;
    if (j < 512) Wcat[i] = Wi[(size_t)r * 512 + j] - Wi[(size_t)(128 + r) * 512 + j];
    else         Wcat[i] = Wi[(size_t)(128 + r) * 512 + (j - 512)];
}
__global__ void wadall_kernel(const float* __restrict__ gW, const float* __restrict__ gAd,
                              float* __restrict__ wad)
{
    int b = blockIdx.x, j = threadIdx.x;
    float s = 0.f;
    for (int kk = 0; kk < 128; kk++)
        s += gW[((size_t)b * 128 + j) * 128 + kk] * gAd[b * 128 + kk];
    wad[b * 128 + j] = s;
}

// ---------------- batched counting sort ----------------
__global__ void fill_i32_kernel(int* p, int val, int n) {
    int i = blockIdx.x * blockDim.x + threadIdx.x;
    if (i < n) p[i] = val;
}
__global__ void count4_kernel(const int* __restrict__ lld, const int* __restrict__ ppd,
                              const int* __restrict__ lpd, const int* __restrict__ pld,
                              int* __restrict__ hist)
{
    int e = blockIdx.x * blockDim.x + threadIdx.x;
    if (e >= E_TOT) return;
    int d;
    if (e < F_PP)      d = O_LL + lld[e];
    else if (e < F_LP) d = O_PP + ppd[e - F_PP];
    else if (e < F_PL) d = O_LP + lpd[e - F_LP];
    else               d = O_PL + pld[e - F_PL];
    atomicAdd(hist + d, 1);
}
__global__ void scan1_kernel(const int* __restrict__ hist, int* __restrict__ off,
                             int* __restrict__ bsum, int n) {
    __shared__ int sh[SCAN_B];
    int tid = threadIdx.x, i = blockIdx.x * SCAN_B + tid;
    int v = (i < n) ? hist[i] : 0;
    sh[tid] = v; __syncthreads();
    for (int d = 1; d < SCAN_B; d <<= 1) {
        int t2 = (tid >= d) ? sh[tid - d] : 0;
        __syncthreads(); sh[tid] += t2; __syncthreads();
    }
    if (i < n) off[i] = sh[tid] - v;
    if (tid == SCAN_B - 1) bsum[blockIdx.x] = sh[tid];
}
__global__ void scan2_kernel(int* __restrict__ bsum, int nb) {
    __shared__ int sh[SCAN_B];
    int tid = threadIdx.x;
    int v = (tid < nb) ? bsum[tid] : 0;
    sh[tid] = v; __syncthreads();
    for (int d = 1; d < SCAN_B; d <<= 1) {
        int t2 = (tid >= d) ? sh[tid - d] : 0;
        __syncthreads(); sh[tid] += t2; __syncthreads();
    }
    if (tid < nb) bsum[tid] = sh[tid] - v;
}
__global__ void scan3_kernel(const int* __restrict__ off, const int* __restrict__ bsum,
                             int* __restrict__ work,
                             int* __restrict__ rp_ll, int* __restrict__ rp_lp,
                             int* __restrict__ rp_pl)
{
    int i = blockIdx.x * blockDim.x + threadIdx.x;
    if (i < NT_NODES) {
        int v = off[i] + bsum[i / SCAN_B];
        work[i] = v;
        if (i < O_PP)                       rp_ll[i] = v - F_LL;
        else if (i >= O_LP && i < O_PL)     rp_lp[i - O_LP] = v - F_LP;
        else if (i >= O_PL)                 rp_pl[i - O_PL] = v - F_PL;
    }
    if (i == 0) {
        rp_ll[N_LEGO]  = NE_LL;
        rp_lp[N_POINT] = NE_LP;
        rp_pl[N_LEGO]  = NE_PL;
    }
}
__global__ void scatter4_kernel(
    const int* __restrict__ lls, const int* __restrict__ lld,
    const int* __restrict__ pps, const int* __restrict__ ppd,
    const int* __restrict__ lps, const int* __restrict__ lpd,
    const int* __restrict__ pls, const int* __restrict__ pld,
    int* __restrict__ work,
    int* __restrict__ oll, int* __restrict__ opp_s, int* __restrict__ opp_d,
    int* __restrict__ olp, int* __restrict__ opl)
{
    int e = blockIdx.x * blockDim.x + threadIdx.x;
    if (e >= E_TOT) return;
    if (e < F_PP) {
        int d = lld[e];
        int pos = atomicAdd(work + O_LL + d, 1);
        oll[pos - F_LL] = lls[e];
    } else if (e < F_LP) {
        int el = e - F_PP;
        int d = ppd[el];
        int pos = atomicAdd(work + O_PP + d, 1) - F_PP;
        opp_s[pos] = pps[el];
        opp_d[pos] = d;
    } else if (e < F_PL) {
        int el = e - F_LP;
        int d = lpd[el];
        int pos = atomicAdd(work + O_LP + d, 1);
        olp[pos - F_LP] = lps[el];
    } else {
        int el = e - F_PL;
        int d = pld[el];
        int pos = atomicAdd(work + O_PL + d, 1);
        opl[pos - F_PL] = pls[el];
    }
}

// ---------------- small glue kernels ----------------
__global__ void fill_u32_kernel(unsigned* p, unsigned val, int n) {
    int i = blockIdx.x * blockDim.x + threadIdx.x;
    if (i < n) p[i] = val;
}
__global__ void node_dot_kernel(const float* __restrict__ h, const float* __restrict__ avec,
                                float* __restrict__ out, int n)
{
    int idx = blockIdx.x * blockDim.x + threadIdx.x;
    int i = idx >> 5, lane = idx & 31;
    if (i >= n) return;
    float4 hv = *(const float4*)(h + (size_t)i * DIMF + lane * 4);
    float4 av = *(const float4*)(avec + lane * 4);
    float s = hv.x * av.x + hv.y * av.y + hv.z * av.z + hv.w * av.w;
#pragma unroll
    for (int o = 16; o; o >>= 1) s += __shfl_xor_sync(0xffffffffu, s, o);
    if (lane == 0) out[i] = s;
}
__global__ void finalize_max_b2_kernel(unsigned* __restrict__ emax,
                                       const float* __restrict__ b2,
                                       float* __restrict__ out, int total) {
    int i = blockIdx.x * blockDim.x + threadIdx.x;
    if (i >= total) return;
    float v = fdecode(emax[i]);
    out[i] = isfinite(v) ? v + b2[i & (DIMF - 1)] : 0.f;
    emax[i] = NEG_INF_KEY;
}

// ---------------- host orchestration ----------------
static inline int div_up(int a, int b) { return (a + b - 1) / b; }

struct Scratch {
    float *xl, *xp, *la, *pa, *hs, *ss, *sd, *escore, *PQ;
    float *WcatT, *bcatT, *WcatE, *wadall;
    unsigned *emax;
    int *hist4, *work4, *bsum;
    int *sll_s, *spp_s, *spp_d, *slp_s, *spl_s;
    int *rp_ll, *rp_lp, *rp_pl;
};

static void sgemm(const float* A, const float* B, const float* bias, float* C,
                  int M, int N, int K) {
    dim3 grid(N / 128, div_up(M, 128));
    bf3_gemm_kernel<<<grid, 256, SMEM_BYTES>>>(A, B, bias, C, M, N, K);
}

static void run_trans(const Scratch& S, const float* x, int n, int inst,
                      const int* rowptr, const int* srcs, float* out)
{
    sgemm(x, S.WcatT + (size_t)inst * 128 * 512, S.bcatT + inst * 512, S.PQ, n, 512, DIMF);
    float scale = 1.f / sqrtf((float)DIMF);
    trans_fused_kernel<<<div_up(n * 32, 256), 256>>>(S.PQ, rowptr, srcs, out, n, scale);
}

static void run_gat(const Scratch& S, const float* xs, int ns, const float* xd, int nd,
                    const int* rowptr, const int* srcs, int inst,
                    const float* W, const float* a_src, const float* gb, float* out)
{
    sgemm(xs, W, nullptr, S.hs, ns, DIMF, DIMF);
    node_dot_kernel<<<div_up(ns * 32, 256), 256>>>(S.hs, a_src, S.ss, ns);
    node_dot_kernel<<<div_up(nd * 32, 256), 256>>>(xd, S.wadall + inst * 128, S.sd, nd);
    gat_fused_kernel<<<div_up(nd * 32, 256), 256>>>(S.ss, S.sd, S.hs, rowptr, srcs,
                                                    S.escore, gb, out, nd);
}

static void run_edge(const Scratch& S, const float* x, int n, int inst,
                     const int* src, const int* dst, int E,
                     const float* b1, const float* W2, const float* b2, float* out)
{
    sgemm(x, S.WcatE + (size_t)inst * 128 * 1024, nullptr, S.PQ, n, 1024, DIMF);
    dim3 grid(1, div_up(E, 128));
    edge_bf3_kernel<<<grid, 256, SMEM_BYTES>>>(S.PQ, b1, W2, src, dst, S.emax, E);
    finalize_max_b2_kernel<<<div_up(n * DIMF, 256), 256>>>(S.emax, b2, out, n * DIMF);
}

extern "C" void kernel_launch(void* const* d_in, const int* in_sizes, int n_in,
                              void* d_out, int out_size)
{
    const float* x_lego  = (const float*)d_in[0];
    const float* x_point = (const float*)d_in[1];
    const float* tWq = (const float*)d_in[2];
    const float* tbq = (const float*)d_in[3];
    const float* tWk = (const float*)d_in[4];
    const float* tbk = (const float*)d_in[5];
    const float* tWv = (const float*)d_in[6];
    const float* tbv = (const float*)d_in[7];
    const float* tWs = (const float*)d_in[8];
    const float* tbs = (const float*)d_in[9];
    const float* eW1 = (const float*)d_in[10];
    const float* eb1 = (const float*)d_in[11];
    const float* eW2 = (const float*)d_in[12];
    const float* eb2 = (const float*)d_in[13];
    const float* gW  = (const float*)d_in[14];
    const float* gAs = (const float*)d_in[15];
    const float* gAd = (const float*)d_in[16];
    const float* gb  = (const float*)d_in[17];
    const int* ll_src = (const int*)d_in[18];
    const int* ll_dst = (const int*)d_in[19];
    const int* pp_src = (const int*)d_in[20];
    const int* pp_dst = (const int*)d_in[21];
    const int* lp_src = (const int*)d_in[22];
    const int* lp_dst = (const int*)d_in[23];
    const int* pl_src = (const int*)d_in[24];
    const int* pl_dst = (const int*)d_in[25];

    cudaFuncSetAttribute(bf3_gemm_kernel, cudaFuncAttributeMaxDynamicSharedMemorySize,
                         SMEM_BYTES);
    cudaFuncSetAttribute(edge_bf3_kernel, cudaFuncAttributeMaxDynamicSharedMemorySize,
                         SMEM_BYTES);

    Scratch S;
    cudaGetSymbolAddress((void**)&S.xl, g_xl);
    cudaGetSymbolAddress((void**)&S.xp, g_xp);
    cudaGetSymbolAddress((void**)&S.la, g_la);
    cudaGetSymbolAddress((void**)&S.pa, g_pa);
    cudaGetSymbolAddress((void**)&S.hs, g_hs);
    cudaGetSymbolAddress((void**)&S.ss, g_ss);
    cudaGetSymbolAddress((void**)&S.sd, g_sd);
    cudaGetSymbolAddress((void**)&S.escore, g_escore);
    cudaGetSymbolAddress((void**)&S.PQ, g_PQ);
    cudaGetSymbolAddress((void**)&S.emax, g_emax);
    cudaGetSymbolAddress((void**)&S.WcatT, g_WcatT);
    cudaGetSymbolAddress((void**)&S.bcatT, g_bcatT);
    cudaGetSymbolAddress((void**)&S.WcatE, g_WcatE);
    cudaGetSymbolAddress((void**)&S.wadall, g_wadall);
    cudaGetSymbolAddress((void**)&S.hist4, g_hist4);
    cudaGetSymbolAddress((void**)&S.work4, g_work4);
    cudaGetSymbolAddress((void**)&S.bsum, g_bsum);
    cudaGetSymbolAddress((void**)&S.sll_s, g_sll_s);
    cudaGetSymbolAddress((void**)&S.spp_s, g_spp_s);
    cudaGetSymbolAddress((void**)&S.spp_d, g_spp_d);
    cudaGetSymbolAddress((void**)&S.slp_s, g_slp_s);
    cudaGetSymbolAddress((void**)&S.spl_s, g_spl_s);
    cudaGetSymbolAddress((void**)&S.rp_ll, g_rp_ll);
    cudaGetSymbolAddress((void**)&S.rp_lp, g_rp_lp);
    cudaGetSymbolAddress((void**)&S.rp_pl, g_rp_pl);

    cudaMemcpyAsync(S.xl, x_lego,  (size_t)N_LEGO * DIMF * sizeof(float),  cudaMemcpyDeviceToDevice);
    cudaMemcpyAsync(S.xp, x_point, (size_t)N_POINT * DIMF * sizeof(float), cudaMemcpyDeviceToDevice);

    concat_trans_kernel<<<div_up(4 * 128 * 512, 256), 256>>>(tWq, tWk, tWv, tWs,
                                                             tbq, tbk, tbv, tbs,
                                                             S.WcatT, S.bcatT);
    concat_edge_kernel<<<div_up(4 * 128 * 1024, 256), 256>>>(eW1, S.WcatE);
    wadall_kernel<<<4, 128>>>(gW, gAd, S.wadall);
    fill_u32_kernel<<<div_up(N_POINT * DIMF, 256), 256>>>(S.emax, NEG_INF_KEY, N_POINT * DIMF);

    fill_i32_kernel<<<div_up(NT_NODES, 256), 256>>>(S.hist4, 0, NT_NODES);
    count4_kernel<<<div_up(E_TOT, 256), 256>>>(ll_dst, pp_dst, lp_dst, pl_dst, S.hist4);
    int nb = div_up(NT_NODES, SCAN_B);
    scan1_kernel<<<nb, SCAN_B>>>(S.hist4, S.work4, S.bsum, NT_NODES);
    scan2_kernel<<<1, SCAN_B>>>(S.bsum, nb);
    scan3_kernel<<<div_up(NT_NODES, 256), 256>>>(S.work4, S.bsum, S.hist4,
                                                 S.rp_ll, S.rp_lp, S.rp_pl);
    scatter4_kernel<<<div_up(E_TOT, 256), 256>>>(ll_src, ll_dst, pp_src, pp_dst,
                                                 lp_src, lp_dst, pl_src, pl_dst,
                                                 S.hist4, S.sll_s, S.spp_s, S.spp_d,
                                                 S.slp_s, S.spl_s);

    for (int layer = 0; layer < 2; layer++) {
        int iA = 2 * layer, iB = 2 * layer + 1;
        int i_lp = 2 * layer, i_pl = 2 * layer + 1;

        run_trans(S, S.xl, N_LEGO, iA, S.rp_ll, S.sll_s, S.la);
        run_gat(S, S.xp, N_POINT, S.xl, N_LEGO, S.rp_pl, S.spl_s, i_pl,
                gW + i_pl * DIMF * DIMF, gAs + i_pl * DIMF, gb + i_pl * DIMF, S.la);

        run_edge(S, S.xp, N_POINT, iA, S.spp_s, S.spp_d, NE_PP,
                 eb1 + iA * 512, eW2 + (size_t)iA * 512 * DIMF, eb2 + iA * DIMF, S.pa);
        run_gat(S, S.xl, N_LEGO, S.xp, N_POINT, S.rp_lp, S.slp_s, i_lp,
                gW + i_lp * DIMF * DIMF, gAs + i_lp * DIMF, gb + i_lp * DIMF, S.pa);

        run_trans(S, S.la, N_LEGO, iB, S.rp_ll, S.sll_s, S.xl);
        run_edge(S, S.pa, N_POINT, iB, S.spp_s, S.spp_d, NE_PP,
                 eb1 + iB * 512, eW2 + (size_t)iB * 512 * DIMF, eb2 + iB * DIMF, S.xp);
    }

    float* out = (float*)d_out;
    cudaMemcpyAsync(out, S.xl, (size_t)N_LEGO * DIMF * sizeof(float), cudaMemcpyDeviceToDevice);
    cudaMemcpyAsync(out + (size_t)N_LEGO * DIMF, S.xp, (size_t)N_POINT * DIMF * sizeof(float),
                    cudaMemcpyDeviceToDevice);
}